// round 1
// baseline (speedup 1.0000x reference)
#include <cuda_runtime.h>
#include <math.h>
#include <stdint.h>

// ---------------- scratch (device globals; no allocation allowed) ----------------
#define BB 2048
__device__ float g_h1[(size_t)BB*32*28*28];   // encoder conv1 out
__device__ float g_h2[(size_t)BB*64*14*14];   // encoder conv2 out
__device__ float g_h3[(size_t)BB*128*7*7];    // encoder conv3 out
__device__ float g_z [(size_t)BB*64];         // latent
__device__ int   g_eidx[BB];                  // selected expert per sample
__device__ float g_dfc[(size_t)BB*32*7*7];    // decoder fc out
__device__ float g_dh1[(size_t)BB*64*14*14];  // decoder conv1 out
__device__ float g_dh2[(size_t)BB*32*28*28];  // decoder conv2 out

// ---------------- encoder conv1 (1->32, 28x28, relu) ----------------
__global__ void k_enc_conv1(const float* __restrict__ x, const float* __restrict__ w,
                            const float* __restrict__ b, float* __restrict__ out) {
    __shared__ float sin_[784];
    __shared__ float sw[288];
    __shared__ float sb[32];
    int n = blockIdx.x, tid = threadIdx.x;
    const float* xin = x + (size_t)n * 784;
    for (int i = tid; i < 784; i += 256) sin_[i] = xin[i];
    for (int i = tid; i < 288; i += 256) sw[i] = w[i];
    if (tid < 32) sb[tid] = b[tid];
    __syncthreads();
    for (int p = tid; p < 784; p += 256) {
        int oy = p / 28, ox = p % 28;
        float v[9];
#pragma unroll
        for (int ky = 0; ky < 3; ky++)
#pragma unroll
            for (int kx = 0; kx < 3; kx++) {
                int iy = oy - 1 + ky, ix = ox - 1 + kx;
                v[ky*3+kx] = (iy >= 0 && iy < 28 && ix >= 0 && ix < 28) ? sin_[iy*28+ix] : 0.f;
            }
        for (int co = 0; co < 32; co++) {
            float a = sb[co];
#pragma unroll
            for (int t = 0; t < 9; t++) a += v[t] * sw[co*9+t];
            out[((size_t)n*32 + co)*784 + p] = fmaxf(a, 0.f);
        }
    }
}

// ---------------- generic direct 3x3 conv, padded-smem staged per input channel --------
// ACT: 0=relu 1=elu 2=sigmoid
template<int CIN, int CO_B, int OH, int OW, int SRC_H, int SRC_W,
         int STRIDE, int UP, int ACT, int NT, int PPT>
__global__ void __launch_bounds__(NT)
conv_k(const float* __restrict__ in, const float* __restrict__ wt,
       const float* __restrict__ bias, float* __restrict__ out, int cout,
       const int* __restrict__ eidx, long wstride, long bstride) {
    constexpr int IH = UP ? SRC_H*2 : SRC_H;
    constexpr int IW = UP ? SRC_W*2 : SRC_W;
    constexpr int PH = (OH-1)*STRIDE + 3;
    constexpr int PW = (OW-1)*STRIDE + 3;
    constexpr int NPIX = OH*OW;
    __shared__ float sp[PH*PW];
    __shared__ float sw[CO_B*9];
    __shared__ float sb[CO_B];

    int n = blockIdx.x;
    int cob = blockIdx.y;
    int tid = threadIdx.x;
    const float* wbase = wt;
    const float* bbase = bias;
    if (eidx) { int e = eidx[n]; wbase += (size_t)e * wstride; bbase += (size_t)e * bstride; }
    const float* inn = in + (size_t)n * CIN * SRC_H * SRC_W;

    if (tid < CO_B) sb[tid] = bbase[cob*CO_B + tid];

    float acc[PPT][CO_B];
#pragma unroll
    for (int pp = 0; pp < PPT; pp++)
#pragma unroll
        for (int c = 0; c < CO_B; c++) acc[pp][c] = 0.f;

    for (int ci = 0; ci < CIN; ci++) {
        const float* src = inn + (size_t)ci * SRC_H * SRC_W;
        // stage zero-padded (and optionally 2x-nearest-upsampled) channel
        for (int i = tid; i < PH*PW; i += NT) {
            int py = i / PW, px = i % PW;
            int iy = py - 1, ix = px - 1;
            float v = 0.f;
            if (iy >= 0 && iy < IH && ix >= 0 && ix < IW) {
                if (UP) v = src[(iy >> 1) * SRC_W + (ix >> 1)];
                else    v = src[iy * SRC_W + ix];
            }
            sp[i] = v;
        }
        for (int i = tid; i < CO_B*9; i += NT) {
            int c = i / 9, t = i % 9;
            sw[i] = wbase[((size_t)(cob*CO_B + c) * CIN + ci) * 9 + t];
        }
        __syncthreads();
#pragma unroll
        for (int pp = 0; pp < PPT; pp++) {
            int p = tid + pp*NT;
            int pc = (p < NPIX) ? p : 0;
            int oy = pc / OW, ox = pc % OW;
            float v[9];
#pragma unroll
            for (int ky = 0; ky < 3; ky++)
#pragma unroll
                for (int kx = 0; kx < 3; kx++)
                    v[ky*3+kx] = sp[(oy*STRIDE + ky)*PW + ox*STRIDE + kx];
#pragma unroll
            for (int c = 0; c < CO_B; c++) {
#pragma unroll
                for (int t = 0; t < 9; t++)
                    acc[pp][c] += v[t] * sw[c*9+t];
            }
        }
        __syncthreads();
    }
#pragma unroll
    for (int pp = 0; pp < PPT; pp++) {
        int p = tid + pp*NT;
        if (p < NPIX) {
#pragma unroll
            for (int c = 0; c < CO_B; c++) {
                float r = acc[pp][c] + sb[c];
                if (ACT == 0)      r = fmaxf(r, 0.f);
                else if (ACT == 1) r = (r > 0.f) ? r : expm1f(r);
                else               r = 1.f / (1.f + expf(-r));
                out[((size_t)n * cout + cob*CO_B + c) * (size_t)NPIX + p] = r;
            }
        }
    }
}

// ---------------- fc for mu / log_var: [2048,6272] x [6272,64], K split 4, atomics ----
__global__ void __launch_bounds__(256)
k_fc(const float* __restrict__ A, const float* __restrict__ W,
     const float* __restrict__ bias, float* __restrict__ O) {
    __shared__ float sa[32][33];
    __shared__ float sb[32][64];
    int mblk = blockIdx.x;     // 64 blocks of 32 rows
    int kz   = blockIdx.y;     // 4 K-splits of 1568
    int tid = threadIdx.x;
    int tx = tid % 16, ty = tid / 16;
    float acc[2][4] = {};
    int row0 = mblk * 32;
    int k0 = kz * 1568;
    for (int it = 0; it < 49; it++) {
        int kb = k0 + it * 32;
        for (int i = tid; i < 32*32; i += 256) {
            int r = i >> 5, c = i & 31;
            sa[r][c] = A[(size_t)(row0 + r) * 6272 + kb + c];
        }
        for (int i = tid; i < 32*64; i += 256) {
            int r = i >> 6, c = i & 63;
            sb[r][c] = W[(size_t)(kb + r) * 64 + c];
        }
        __syncthreads();
#pragma unroll
        for (int kk = 0; kk < 32; kk++) {
            float a0 = sa[ty*2][kk], a1 = sa[ty*2+1][kk];
#pragma unroll
            for (int j = 0; j < 4; j++) {
                float bv = sb[kk][tx*4+j];
                acc[0][j] += a0 * bv;
                acc[1][j] += a1 * bv;
            }
        }
        __syncthreads();
    }
#pragma unroll
    for (int i = 0; i < 2; i++)
#pragma unroll
        for (int j = 0; j < 4; j++) {
            int r = row0 + ty*2 + i, c = tx*4 + j;
            float v = acc[i][j];
            if (kz == 0) v += bias[c];
            atomicAdd(&O[(size_t)r*64 + c], v);
        }
}

// ---------------- z sample + gating MLP + softmax + argmax ----------------
__global__ void __launch_bounds__(64)
k_gate(const float* __restrict__ mu, const float* __restrict__ lv, const float* __restrict__ eps,
       const float* __restrict__ w1, const float* __restrict__ b1,
       const float* __restrict__ w2, const float* __restrict__ b2,
       const float* __restrict__ w3, const float* __restrict__ b3,
       float* __restrict__ logits_out, float* __restrict__ probs_out) {
    int n = blockIdx.x, t = threadIdx.x;
    __shared__ float zz[64], h1[64], h2[32], lg[8];
    float m = mu[(size_t)n*64 + t], l = lv[(size_t)n*64 + t];
    float z = m + eps[(size_t)n*64 + t] * expf(0.5f * l);
    zz[t] = z;
    g_z[(size_t)n*64 + t] = z;
    __syncthreads();
    float a = b1[t];
    for (int k = 0; k < 64; k++) a += zz[k] * w1[k*64 + t];
    h1[t] = fmaxf(a, 0.f);
    __syncthreads();
    if (t < 32) {
        float a2 = b2[t];
        for (int k = 0; k < 64; k++) a2 += h1[k] * w2[k*32 + t];
        h2[t] = fmaxf(a2, 0.f);
    }
    __syncthreads();
    if (t < 8) {
        float a3 = b3[t];
        for (int k = 0; k < 32; k++) a3 += h2[k] * w3[k*8 + t];
        lg[t] = a3;
    }
    __syncthreads();
    if (t == 0) {
        float mx = lg[0];
        for (int i = 1; i < 8; i++) mx = fmaxf(mx, lg[i]);
        float e[8], s = 0.f;
        for (int i = 0; i < 8; i++) { e[i] = expf(lg[i] - mx); s += e[i]; }
        float inv = 1.f / s;
        int best = 0; float bp = -1.f;
        for (int i = 0; i < 8; i++) {
            float p = e[i] * inv;
            probs_out[(size_t)n*8 + i] = p;
            logits_out[(size_t)n*8 + i] = logf(p + 1e-8f);
            if (p > bp) { bp = p; best = i; }   // first-max, matches jnp.argmax
        }
        g_eidx[n] = best;
    }
}

// ---------------- decoder fc (selected expert): z[64] @ W_e[64,1568] ----------------
__global__ void __launch_bounds__(256)
k_dec_fc(const float* __restrict__ fcw, const float* __restrict__ fcb) {
    int n = blockIdx.x, t = threadIdx.x;
    __shared__ float zz[64];
    int e = g_eidx[n];
    if (t < 64) zz[t] = g_z[(size_t)n*64 + t];
    __syncthreads();
    const float* W = fcw + (size_t)e * 64 * 1568;
    const float* B = fcb + (size_t)e * 1568;
    for (int o = t; o < 1568; o += 256) {
        float a = B[o];
#pragma unroll 8
        for (int k = 0; k < 64; k++) a += zz[k] * W[(size_t)k*1568 + o];
        g_dfc[(size_t)n*1568 + o] = a;
    }
}

// ---------------- launcher ----------------
extern "C" void kernel_launch(void* const* d_in, const int* in_sizes, int n_in,
                              void* d_out, int out_size) {
    const float* x      = (const float*)d_in[0];
    const float* eps    = (const float*)d_in[1];
    const float* enc_w1 = (const float*)d_in[2];  const float* enc_b1 = (const float*)d_in[3];
    const float* enc_w2 = (const float*)d_in[4];  const float* enc_b2 = (const float*)d_in[5];
    const float* enc_w3 = (const float*)d_in[6];  const float* enc_b3 = (const float*)d_in[7];
    const float* w_mu   = (const float*)d_in[8];  const float* b_mu   = (const float*)d_in[9];
    const float* w_lv   = (const float*)d_in[10]; const float* b_lv   = (const float*)d_in[11];
    const float* g_w1   = (const float*)d_in[12]; const float* g_b1   = (const float*)d_in[13];
    const float* g_w2   = (const float*)d_in[14]; const float* g_b2   = (const float*)d_in[15];
    const float* g_w3   = (const float*)d_in[16]; const float* g_b3   = (const float*)d_in[17];
    const float* d_fc_w = (const float*)d_in[18]; const float* d_fc_b = (const float*)d_in[19];
    const float* d_w1   = (const float*)d_in[20]; const float* d_b1   = (const float*)d_in[21];
    const float* d_w2   = (const float*)d_in[22]; const float* d_b2   = (const float*)d_in[23];
    const float* d_w3   = (const float*)d_in[24]; const float* d_b3   = (const float*)d_in[25];

    float* out   = (float*)d_out;
    float* o_rec = out;                       // [2048,1,28,28]
    float* o_mu  = out + (size_t)BB*784;      // [2048,64]
    float* o_lv  = o_mu + (size_t)BB*64;      // [2048,64]
    float* o_lg  = o_lv + (size_t)BB*64;      // [2048,8]
    float* o_pb  = o_lg + (size_t)BB*8;       // [2048,8]

    float *h1, *h2, *h3, *dfc, *dh1, *dh2; int* eidx;
    cudaGetSymbolAddress((void**)&h1,  g_h1);
    cudaGetSymbolAddress((void**)&h2,  g_h2);
    cudaGetSymbolAddress((void**)&h3,  g_h3);
    cudaGetSymbolAddress((void**)&dfc, g_dfc);
    cudaGetSymbolAddress((void**)&dh1, g_dh1);
    cudaGetSymbolAddress((void**)&dh2, g_dh2);
    cudaGetSymbolAddress((void**)&eidx, g_eidx);

    // mu/lv accumulated with atomics -> zero first (d_out is poisoned)
    cudaMemsetAsync(o_mu, 0, (size_t)BB*128*sizeof(float));

    // encoder
    k_enc_conv1<<<BB, 256>>>(x, enc_w1, enc_b1, h1);
    conv_k<32, 32, 14,14, 28,28, 2, 0, 0, 224, 1><<<dim3(BB,2), 224>>>(h1, enc_w2, enc_b2, h2, 64, nullptr, 0, 0);
    conv_k<64, 32,  7, 7, 14,14, 2, 0, 0,  64, 1><<<dim3(BB,4),  64>>>(h2, enc_w3, enc_b3, h3, 128, nullptr, 0, 0);

    // mu / log_var
    k_fc<<<dim3(64,4), 256>>>(h3, w_mu, b_mu, o_mu);
    k_fc<<<dim3(64,4), 256>>>(h3, w_lv, b_lv, o_lv);

    // gating + expert selection
    k_gate<<<BB, 64>>>(o_mu, o_lv, eps, g_w1, g_b1, g_w2, g_b2, g_w3, g_b3, o_lg, o_pb);

    // decoder: ONLY the selected expert per sample (output-equivalent to running all 8)
    k_dec_fc<<<BB, 256>>>(d_fc_w, d_fc_b);
    conv_k<32, 32, 14,14,  7, 7, 1, 1, 1, 224, 1><<<dim3(BB,2), 224>>>(dfc, d_w1, d_b1, dh1, 64, eidx, (long)64*32*9, 64);
    conv_k<64, 16, 28,28, 14,14, 1, 1, 1, 256, 4><<<dim3(BB,2), 256>>>(dh1, d_w2, d_b2, dh2, 32, eidx, (long)32*64*9, 32);
    conv_k<32,  1, 28,28, 28,28, 1, 0, 2, 256, 4><<<dim3(BB,1), 256>>>(dh2, d_w3, d_b3, o_rec, 1, eidx, (long)1*32*9, 1);
}

// round 2
// speedup vs baseline: 1.2182x; 1.2182x over previous
#include <cuda_runtime.h>
#include <math.h>
#include <stdint.h>

#define BB 2048
typedef unsigned long long ull;

// ---------------- f32x2 packed-math helpers ----------------
__device__ __forceinline__ ull dup2(float v) {
    unsigned x = __float_as_uint(v); ull r;
    asm("mov.b64 %0, {%1, %1};" : "=l"(r) : "r"(x));
    return r;
}
__device__ __forceinline__ ull pack2(float a, float b) {
    unsigned x = __float_as_uint(a), y = __float_as_uint(b); ull r;
    asm("mov.b64 %0, {%1, %2};" : "=l"(r) : "r"(x), "r"(y));
    return r;
}
__device__ __forceinline__ void fma2(ull& d, ull a, ull b) {
    asm("fma.rn.f32x2 %0, %1, %2, %0;" : "+l"(d) : "l"(a), "l"(b));
}
__device__ __forceinline__ float2 unpack2(ull v) {
    unsigned x, y;
    asm("mov.b64 {%0, %1}, %2;" : "=r"(x), "=r"(y) : "l"(v));
    float2 f; f.x = __uint_as_float(x); f.y = __uint_as_float(y); return f;
}

// ---------------- scratch (device globals) ----------------
__device__ float g_h1[(size_t)BB*32*28*28];
__device__ float g_h2[(size_t)BB*64*14*14];
__device__ float g_h3[(size_t)BB*128*7*7];
__device__ float g_z [(size_t)BB*64];
__device__ int   g_eidx[BB];
__device__ float g_dfc[(size_t)BB*32*7*7];
__device__ float g_dh1[(size_t)BB*64*14*14];
__device__ float g_dh2[(size_t)BB*32*28*28];

// ---------------- encoder conv1 (1->32, 28x28, relu) ----------------
__global__ void k_enc_conv1(const float* __restrict__ x, const float* __restrict__ w,
                            const float* __restrict__ b, float* __restrict__ out) {
    __shared__ float sin_[784];
    __shared__ float sw[288];
    __shared__ float sb[32];
    int n = blockIdx.x, tid = threadIdx.x;
    const float* xin = x + (size_t)n * 784;
    for (int i = tid; i < 784; i += 256) sin_[i] = xin[i];
    for (int i = tid; i < 288; i += 256) sw[i] = w[i];
    if (tid < 32) sb[tid] = b[tid];
    __syncthreads();
    for (int p = tid; p < 784; p += 256) {
        int oy = p / 28, ox = p % 28;
        float v[9];
#pragma unroll
        for (int ky = 0; ky < 3; ky++)
#pragma unroll
            for (int kx = 0; kx < 3; kx++) {
                int iy = oy - 1 + ky, ix = ox - 1 + kx;
                v[ky*3+kx] = (iy >= 0 && iy < 28 && ix >= 0 && ix < 28) ? sin_[iy*28+ix] : 0.f;
            }
        for (int co = 0; co < 32; co++) {
            float a = sb[co];
#pragma unroll
            for (int t = 0; t < 9; t++) a += v[t] * sw[co*9+t];
            out[((size_t)n*32 + co)*784 + p] = fmaxf(a, 0.f);
        }
    }
}

// ---------------- generic f32x2 cout-pair-packed 3x3 conv ----------------
// spad: zero-padded SOURCE-resolution channel images (upsample folded into tap idx)
// sw2:  weights packed as float2 over cout pairs
// ACT: 0=relu 1=elu 2=sigmoid
template<int CIN,int COUT,int CO_B,int OH,int OW,int SH,int SW_,int STRIDE,int UP,int ACT,
         int NT,int PPT,int SB,int CI_T>
__global__ void __launch_bounds__(NT)
conv2k(const float* __restrict__ in, const float* __restrict__ wt,
       const float* __restrict__ bs, float* __restrict__ out, const int* __restrict__ eidx) {
    constexpr int PW_ = SW_ + 2, PH_ = SH + 2, PA = PW_ * PH_;
    constexpr int NPIX = OH * OW, CO2 = CO_B / 2;
    static_assert(NT * PPT == SB * NPIX, "coverage");
    static_assert(CIN % CI_T == 0, "citile");
    static_assert(((SB * CI_T * PA) & 1) == 0, "align8");

    extern __shared__ ull dsm[];
    float* sp = (float*)dsm;
    ull* sw2 = dsm + (size_t)(SB * CI_T * PA) / 2;
    __shared__ float sbias[CO_B];

    const int tid = threadIdx.x;
    const int nb = blockIdx.x * SB;
    const int cob = blockIdx.y;
    const float* wb = wt;
    const float* bb = bs;
    if (eidx) { int e = eidx[nb]; wb += (size_t)e * COUT * CIN * 9; bb += (size_t)e * COUT; }

    // stage packed weights once
    for (int i = tid; i < CIN * 9 * CO2; i += NT) {
        int ci = i / (9 * CO2); int r = i - ci * 9 * CO2;
        int t = r / CO2; int c2 = r - t * CO2;
        int c0 = cob * CO_B + 2 * c2;
        float w0 = wb[((size_t)c0 * CIN + ci) * 9 + t];
        float w1 = wb[((size_t)(c0 + 1) * CIN + ci) * 9 + t];
        sw2[i] = pack2(w0, w1);
    }
    if (tid < CO_B) sbias[tid] = bb[cob * CO_B + tid];

    // per-thread pixel setup
    int off[PPT][9]; int sbase[PPT]; int sArr[PPT]; int pixArr[PPT];
#pragma unroll
    for (int pp = 0; pp < PPT; pp++) {
        int p = tid + pp * NT;
        int s = p / NPIX; int pix = p - s * NPIX;
        int oy = pix / OW, ox = pix - oy * OW;
        int ry[3], cx[3];
#pragma unroll
        for (int k = 0; k < 3; k++) {
            ry[k] = UP ? (((oy - 1 + k) >> 1) + 1) : (oy * STRIDE + k);
            cx[k] = UP ? (((ox - 1 + k) >> 1) + 1) : (ox * STRIDE + k);
        }
#pragma unroll
        for (int ky = 0; ky < 3; ky++)
#pragma unroll
            for (int kx = 0; kx < 3; kx++) off[pp][ky*3+kx] = ry[ky] * PW_ + cx[kx];
        sbase[pp] = s * CI_T * PA;
        sArr[pp] = s; pixArr[pp] = pix;
    }

    ull acc[PPT][CO2];
#pragma unroll
    for (int pp = 0; pp < PPT; pp++)
#pragma unroll
        for (int c2 = 0; c2 < CO2; c2++) acc[pp][c2] = 0ull;

    for (int ci0 = 0; ci0 < CIN; ci0 += CI_T) {
        __syncthreads();   // also covers weight staging on first pass
        for (int i = tid; i < SB * CI_T * PA; i += NT) {
            int s = i / (CI_T * PA); int r = i - s * CI_T * PA;
            int ci = r / PA; int q = r - ci * PA;
            int py = q / PW_, px = q - py * PW_;
            int iy = py - 1, ix = px - 1;
            float v = 0.f;
            if (iy >= 0 && iy < SH && ix >= 0 && ix < SW_)
                v = in[(((size_t)(nb + s) * CIN + ci0 + ci) * SH + iy) * SW_ + ix];
            sp[i] = v;
        }
        __syncthreads();
        for (int ci = 0; ci < CI_T; ci++) {
            ull v2[PPT][9];
#pragma unroll
            for (int pp = 0; pp < PPT; pp++) {
                const float* cb = sp + sbase[pp] + ci * PA;
#pragma unroll
                for (int t = 0; t < 9; t++) v2[pp][t] = dup2(cb[off[pp][t]]);
            }
            const ull* wrow = sw2 + (size_t)(ci0 + ci) * 9 * CO2;
#pragma unroll
            for (int c2 = 0; c2 < CO2; c2++) {
#pragma unroll
                for (int t = 0; t < 9; t++) {
                    ull wv = wrow[t * CO2 + c2];
#pragma unroll
                    for (int pp = 0; pp < PPT; pp++) fma2(acc[pp][c2], v2[pp][t], wv);
                }
            }
        }
    }

    // epilogue
#pragma unroll
    for (int pp = 0; pp < PPT; pp++) {
        int n = nb + sArr[pp]; int pix = pixArr[pp];
#pragma unroll
        for (int c2 = 0; c2 < CO2; c2++) {
            float2 f = unpack2(acc[pp][c2]);
            int c0 = cob * CO_B + 2 * c2;
            float r0 = f.x + sbias[2*c2];
            float r1 = f.y + sbias[2*c2+1];
            if (ACT == 0)      { r0 = fmaxf(r0, 0.f); r1 = fmaxf(r1, 0.f); }
            else if (ACT == 1) { r0 = r0 > 0.f ? r0 : expm1f(r0); r1 = r1 > 0.f ? r1 : expm1f(r1); }
            else               { r0 = 1.f/(1.f+expf(-r0)); r1 = 1.f/(1.f+expf(-r1)); }
            out[((size_t)n * COUT + c0) * NPIX + pix] = r0;
            out[((size_t)n * COUT + c0 + 1) * NPIX + pix] = r1;
        }
    }
}

// ---------------- fused mu+logvar fc: [2048,6272] x 2x[6272,64], split-K=7 ----------------
__global__ void __launch_bounds__(256)
k_fc2(const float* __restrict__ A,
      const float* __restrict__ Wm, const float* __restrict__ bm,
      const float* __restrict__ Wl, const float* __restrict__ bl,
      float* __restrict__ Om, float* __restrict__ Ol) {
    __shared__ float sa[32][33];
    __shared__ float swm[32][64];
    __shared__ float swl[32][64];
    int tid = threadIdx.x, tx = tid & 15, ty = tid >> 4;
    float am[2][4] = {}, al[2][4] = {};
    int row0 = blockIdx.x * 32;
    int k0 = blockIdx.y * 896;
    for (int it = 0; it < 28; it++) {
        int kb = k0 + it * 32;
        for (int i = tid; i < 32*32; i += 256) { int r = i>>5, c = i&31; sa[r][c] = A[(size_t)(row0+r)*6272 + kb + c]; }
        for (int i = tid; i < 32*64; i += 256) { int r = i>>6, c = i&63;
            swm[r][c] = Wm[(size_t)(kb+r)*64 + c];
            swl[r][c] = Wl[(size_t)(kb+r)*64 + c]; }
        __syncthreads();
#pragma unroll
        for (int kk = 0; kk < 32; kk++) {
            float a0 = sa[ty*2][kk], a1 = sa[ty*2+1][kk];
#pragma unroll
            for (int j = 0; j < 4; j++) {
                float wm_ = swm[kk][tx*4+j], wl_ = swl[kk][tx*4+j];
                am[0][j] += a0 * wm_; am[1][j] += a1 * wm_;
                al[0][j] += a0 * wl_; al[1][j] += a1 * wl_;
            }
        }
        __syncthreads();
    }
#pragma unroll
    for (int i = 0; i < 2; i++)
#pragma unroll
        for (int j = 0; j < 4; j++) {
            int r = row0 + ty*2 + i, c = tx*4 + j;
            float vm = am[i][j], vl = al[i][j];
            if (blockIdx.y == 0) { vm += bm[c]; vl += bl[c]; }
            atomicAdd(&Om[(size_t)r*64 + c], vm);
            atomicAdd(&Ol[(size_t)r*64 + c], vl);
        }
}

// ---------------- z sample + gating MLP + softmax + argmax ----------------
__global__ void __launch_bounds__(64)
k_gate(const float* __restrict__ mu, const float* __restrict__ lv, const float* __restrict__ eps,
       const float* __restrict__ w1, const float* __restrict__ b1,
       const float* __restrict__ w2, const float* __restrict__ b2,
       const float* __restrict__ w3, const float* __restrict__ b3,
       float* __restrict__ logits_out, float* __restrict__ probs_out) {
    int n = blockIdx.x, t = threadIdx.x;
    __shared__ float zz[64], h1[64], h2[32], lg[8];
    float m = mu[(size_t)n*64 + t], l = lv[(size_t)n*64 + t];
    float z = m + eps[(size_t)n*64 + t] * expf(0.5f * l);
    zz[t] = z;
    g_z[(size_t)n*64 + t] = z;
    __syncthreads();
    float a = b1[t];
    for (int k = 0; k < 64; k++) a += zz[k] * w1[k*64 + t];
    h1[t] = fmaxf(a, 0.f);
    __syncthreads();
    if (t < 32) {
        float a2 = b2[t];
        for (int k = 0; k < 64; k++) a2 += h1[k] * w2[k*32 + t];
        h2[t] = fmaxf(a2, 0.f);
    }
    __syncthreads();
    if (t < 8) {
        float a3 = b3[t];
        for (int k = 0; k < 32; k++) a3 += h2[k] * w3[k*8 + t];
        lg[t] = a3;
    }
    __syncthreads();
    if (t == 0) {
        float mx = lg[0];
        for (int i = 1; i < 8; i++) mx = fmaxf(mx, lg[i]);
        float e[8], s = 0.f;
        for (int i = 0; i < 8; i++) { e[i] = expf(lg[i] - mx); s += e[i]; }
        float inv = 1.f / s;
        int best = 0; float bp = -1.f;
        for (int i = 0; i < 8; i++) {
            float p = e[i] * inv;
            probs_out[(size_t)n*8 + i] = p;
            logits_out[(size_t)n*8 + i] = logf(p + 1e-8f);
            if (p > bp) { bp = p; best = i; }
        }
        g_eidx[n] = best;
    }
}

// ---------------- decoder fc (selected expert) ----------------
__global__ void __launch_bounds__(256)
k_dec_fc(const float* __restrict__ fcw, const float* __restrict__ fcb) {
    int n = blockIdx.x, t = threadIdx.x;
    __shared__ float zz[64];
    int e = g_eidx[n];
    if (t < 64) zz[t] = g_z[(size_t)n*64 + t];
    __syncthreads();
    const float* W = fcw + (size_t)e * 64 * 1568;
    const float* B = fcb + (size_t)e * 1568;
    for (int o = t; o < 1568; o += 256) {
        float a = B[o];
#pragma unroll 8
        for (int k = 0; k < 64; k++) a += zz[k] * W[(size_t)k*1568 + o];
        g_dfc[(size_t)n*1568 + o] = a;
    }
}

// ---------------- decoder conv3 (32->1, sigmoid) ----------------
__global__ void __launch_bounds__(196)
k_dconv3(const float* __restrict__ in, const float* __restrict__ wt,
         const float* __restrict__ bs, float* __restrict__ out, const int* __restrict__ eidx) {
    extern __shared__ float sp3[];   // 32*900
    __shared__ float sw[288];
    __shared__ float sb0;
    int n = blockIdx.x, tid = threadIdx.x;
    int e = eidx[n];
    const float* wb = wt + (size_t)e * 288;
    if (tid == 0) sb0 = bs[e];
    for (int i = tid; i < 288; i += 196) sw[i] = wb[i];
    const float* inn = in + (size_t)n * 32 * 784;
    for (int i = tid; i < 32*900; i += 196) {
        int ci = i / 900, q = i - ci*900;
        int py = q / 30, px = q - py*30;
        int iy = py - 1, ix = px - 1;
        float v = 0.f;
        if (iy >= 0 && iy < 28 && ix >= 0 && ix < 28) v = inn[ci*784 + iy*28 + ix];
        sp3[i] = v;
    }
    __syncthreads();
    int off[4][9]; int pixA[4];
#pragma unroll
    for (int pp = 0; pp < 4; pp++) {
        int p = tid + pp*196; pixA[pp] = p;
        int oy = p / 28, ox = p - oy*28;
#pragma unroll
        for (int ky = 0; ky < 3; ky++)
#pragma unroll
            for (int kx = 0; kx < 3; kx++) off[pp][ky*3+kx] = (oy+ky)*30 + (ox+kx);
    }
    float acc[4] = {0.f, 0.f, 0.f, 0.f};
    for (int ci = 0; ci < 32; ci++) {
        float wr[9];
#pragma unroll
        for (int t = 0; t < 9; t++) wr[t] = sw[ci*9 + t];
        const float* cb = sp3 + ci*900;
#pragma unroll
        for (int pp = 0; pp < 4; pp++) {
#pragma unroll
            for (int t = 0; t < 9; t++) acc[pp] += cb[off[pp][t]] * wr[t];
        }
    }
#pragma unroll
    for (int pp = 0; pp < 4; pp++) {
        float r = acc[pp] + sb0;
        out[(size_t)n*784 + pixA[pp]] = 1.f / (1.f + expf(-r));
    }
}

// ---------------- launcher ----------------
extern "C" void kernel_launch(void* const* d_in, const int* in_sizes, int n_in,
                              void* d_out, int out_size) {
    const float* x      = (const float*)d_in[0];
    const float* eps    = (const float*)d_in[1];
    const float* enc_w1 = (const float*)d_in[2];  const float* enc_b1 = (const float*)d_in[3];
    const float* enc_w2 = (const float*)d_in[4];  const float* enc_b2 = (const float*)d_in[5];
    const float* enc_w3 = (const float*)d_in[6];  const float* enc_b3 = (const float*)d_in[7];
    const float* w_mu   = (const float*)d_in[8];  const float* b_mu   = (const float*)d_in[9];
    const float* w_lv   = (const float*)d_in[10]; const float* b_lv   = (const float*)d_in[11];
    const float* g_w1   = (const float*)d_in[12]; const float* g_b1   = (const float*)d_in[13];
    const float* g_w2   = (const float*)d_in[14]; const float* g_b2   = (const float*)d_in[15];
    const float* g_w3   = (const float*)d_in[16]; const float* g_b3   = (const float*)d_in[17];
    const float* d_fc_w = (const float*)d_in[18]; const float* d_fc_b = (const float*)d_in[19];
    const float* d_w1   = (const float*)d_in[20]; const float* d_b1   = (const float*)d_in[21];
    const float* d_w2   = (const float*)d_in[22]; const float* d_b2   = (const float*)d_in[23];
    const float* d_w3   = (const float*)d_in[24]; const float* d_b3   = (const float*)d_in[25];

    float* out   = (float*)d_out;
    float* o_rec = out;
    float* o_mu  = out + (size_t)BB*784;
    float* o_lv  = o_mu + (size_t)BB*64;
    float* o_lg  = o_lv + (size_t)BB*64;
    float* o_pb  = o_lg + (size_t)BB*8;

    float *h1, *h2, *h3, *dfc, *dh1, *dh2; int* eidx;
    cudaGetSymbolAddress((void**)&h1,  g_h1);
    cudaGetSymbolAddress((void**)&h2,  g_h2);
    cudaGetSymbolAddress((void**)&h3,  g_h3);
    cudaGetSymbolAddress((void**)&dfc, g_dfc);
    cudaGetSymbolAddress((void**)&dh1, g_dh1);
    cudaGetSymbolAddress((void**)&dh2, g_dh2);
    cudaGetSymbolAddress((void**)&eidx, g_eidx);

    // conv template instantiations + smem sizes
    // enc2: 32->64, 28x28 s2 -> 14x14
    auto enc2 = conv2k<32,64,32, 14,14, 28,28, 2,0,0, 196,1,1,32>;
    constexpr int SM_ENC2 = 1*32*900*4 + 32*9*16*8;          // 152064
    // enc3: 64->128, 14x14 s2 -> 7x7, 4 samples/block, CI tile 32
    auto enc3 = conv2k<64,128,32, 7,7, 14,14, 2,0,0, 196,1,4,32>;
    constexpr int SM_ENC3 = 4*32*256*4 + 64*9*16*8;          // 204800
    // dec1: 32->64, up 7->14
    auto dec1 = conv2k<32,64,32, 14,14, 7,7, 1,1,1, 196,1,1,32>;
    constexpr int SM_DEC1 = 1*32*81*4 + 32*9*16*8;           // 47232
    // dec2: 64->32, up 14->28
    auto dec2 = conv2k<64,32,16, 28,28, 14,14, 1,1,1, 392,2,1,64>;
    constexpr int SM_DEC2 = 1*64*256*4 + 64*9*8*8;           // 102400
    constexpr int SM_DEC3 = 32*900*4;                         // 115200

    cudaFuncSetAttribute(enc2, cudaFuncAttributeMaxDynamicSharedMemorySize, SM_ENC2);
    cudaFuncSetAttribute(enc3, cudaFuncAttributeMaxDynamicSharedMemorySize, SM_ENC3);
    cudaFuncSetAttribute(dec1, cudaFuncAttributeMaxDynamicSharedMemorySize, SM_DEC1);
    cudaFuncSetAttribute(dec2, cudaFuncAttributeMaxDynamicSharedMemorySize, SM_DEC2);
    cudaFuncSetAttribute(k_dconv3, cudaFuncAttributeMaxDynamicSharedMemorySize, SM_DEC3);

    // mu/lv accumulated with atomics -> zero first
    cudaMemsetAsync(o_mu, 0, (size_t)BB*128*sizeof(float));

    // encoder
    k_enc_conv1<<<BB, 256>>>(x, enc_w1, enc_b1, h1);
    enc2<<<dim3(BB, 2),   196, SM_ENC2>>>(h1, enc_w2, enc_b2, h2, nullptr);
    enc3<<<dim3(BB/4, 4), 196, SM_ENC3>>>(h2, enc_w3, enc_b3, h3, nullptr);

    // mu / log_var fused
    k_fc2<<<dim3(64, 7), 256>>>(h3, w_mu, b_mu, w_lv, b_lv, o_mu, o_lv);

    // gating + expert selection
    k_gate<<<BB, 64>>>(o_mu, o_lv, eps, g_w1, g_b1, g_w2, g_b2, g_w3, g_b3, o_lg, o_pb);

    // decoder: only the selected expert per sample
    k_dec_fc<<<BB, 256>>>(d_fc_w, d_fc_b);
    dec1<<<dim3(BB, 2), 196, SM_DEC1>>>(dfc, d_w1, d_b1, dh1, eidx);
    dec2<<<dim3(BB, 2), 392, SM_DEC2>>>(dh1, d_w2, d_b2, dh2, eidx);
    k_dconv3<<<BB, 196, SM_DEC3>>>(dh2, d_w3, d_b3, o_rec, eidx);
}

// round 3
// speedup vs baseline: 1.3397x; 1.0997x over previous
#include <cuda_runtime.h>
#include <math.h>
#include <stdint.h>

#define BB 2048
typedef unsigned long long ull;

// ---------------- f32x2 packed-math helpers ----------------
__device__ __forceinline__ ull dup2(float v) {
    unsigned x = __float_as_uint(v); ull r;
    asm("mov.b64 %0, {%1, %1};" : "=l"(r) : "r"(x));
    return r;
}
__device__ __forceinline__ ull pack2(float a, float b) {
    unsigned x = __float_as_uint(a), y = __float_as_uint(b); ull r;
    asm("mov.b64 %0, {%1, %2};" : "=l"(r) : "r"(x), "r"(y));
    return r;
}
__device__ __forceinline__ void fma2(ull& d, ull a, ull b) {
    asm("fma.rn.f32x2 %0, %1, %2, %0;" : "+l"(d) : "l"(a), "l"(b));
}
__device__ __forceinline__ float2 unpack2(ull v) {
    unsigned x, y;
    asm("mov.b64 {%0, %1}, %2;" : "=r"(x), "=r"(y) : "l"(v));
    float2 f; f.x = __uint_as_float(x); f.y = __uint_as_float(y); return f;
}

// ---------------- scratch (device globals) ----------------
__device__ float g_h1[(size_t)BB*32*28*28];
__device__ float g_h2[(size_t)BB*64*14*14];
__device__ float g_h3[(size_t)BB*128*7*7];
__device__ float g_z [(size_t)BB*64];
__device__ int   g_eidx[BB];
__device__ float g_dfc[(size_t)BB*32*7*7];
__device__ float g_dh1[(size_t)BB*64*14*14];
__device__ float g_dh2[(size_t)BB*32*28*28];

// ---------------- encoder conv1 (1->32, 28x28, relu) ----------------
__global__ void k_enc_conv1(const float* __restrict__ x, const float* __restrict__ w,
                            const float* __restrict__ b, float* __restrict__ out) {
    __shared__ float sin_[784];
    __shared__ float sw[288];
    __shared__ float sb[32];
    int n = blockIdx.x, tid = threadIdx.x;
    const float* xin = x + (size_t)n * 784;
    for (int i = tid; i < 784; i += 256) sin_[i] = xin[i];
    for (int i = tid; i < 288; i += 256) sw[i] = w[i];
    if (tid < 32) sb[tid] = b[tid];
    __syncthreads();
    for (int p = tid; p < 784; p += 256) {
        int oy = p / 28, ox = p % 28;
        float v[9];
#pragma unroll
        for (int ky = 0; ky < 3; ky++)
#pragma unroll
            for (int kx = 0; kx < 3; kx++) {
                int iy = oy - 1 + ky, ix = ox - 1 + kx;
                v[ky*3+kx] = (iy >= 0 && iy < 28 && ix >= 0 && ix < 28) ? sin_[iy*28+ix] : 0.f;
            }
        for (int co = 0; co < 32; co++) {
            float a = sb[co];
#pragma unroll
            for (int t = 0; t < 9; t++) a += v[t] * sw[co*9+t];
            out[((size_t)n*32 + co)*784 + p] = fmaxf(a, 0.f);
        }
    }
}

// ---------------- f32x2 cout-pair conv, t-outer / c2-inner, PPT-amortized weights ------
// ACT: 0=relu 1=elu 2=sigmoid
template<int CIN,int COUT,int CO_B,int OH,int OW,int SH,int SW_,int STRIDE,int UP,int ACT,
         int NT,int PPT,int SB,int CI_T,int MINB>
__global__ void __launch_bounds__(NT, MINB)
conv3k(const float* __restrict__ in, const float* __restrict__ wt,
       const float* __restrict__ bs, float* __restrict__ out, const int* __restrict__ eidx) {
    constexpr int PW_ = SW_ + 2, PH_ = SH + 2, PA = PW_ * PH_;
    constexpr int NPIX = OH * OW, CO2 = CO_B / 2;
    static_assert(NT * PPT == SB * NPIX, "coverage");
    static_assert(CIN % CI_T == 0, "citile");
    static_assert(((SB * CI_T * PA) & 1) == 0, "align8");

    extern __shared__ ull dsm[];
    float* sp = (float*)dsm;
    ull* sw2 = dsm + (size_t)(SB * CI_T * PA) / 2;
    __shared__ float sbias[CO_B];

    const int tid = threadIdx.x;
    const int nb = blockIdx.x * SB;
    const int cob = blockIdx.y;
    const float* wb = wt;
    const float* bb = bs;
    if (eidx) { int e = eidx[nb]; wb += (size_t)e * COUT * CIN * 9; bb += (size_t)e * COUT; }

    // stage packed weights ONCE: sw2[(ci*9+t)*CO2 + c2]
    for (int i = tid; i < CIN * 9 * CO2; i += NT) {
        int ci = i / (9 * CO2); int r = i - ci * 9 * CO2;
        int t = r / CO2; int c2 = r - t * CO2;
        int c0 = cob * CO_B + 2 * c2;
        float w0 = wb[((size_t)c0 * CIN + ci) * 9 + t];
        float w1 = wb[((size_t)(c0 + 1) * CIN + ci) * 9 + t];
        sw2[(ci * 9 + t) * CO2 + c2] = pack2(w0, w1);
    }
    if (tid < CO_B) sbias[tid] = bb[cob * CO_B + tid];

    // per-thread pixel setup
    int off[PPT][UP ? 9 : 1];      // full tap offsets for UP; base only for strided
    int sbase[PPT]; int sArr[PPT]; int pixArr[PPT];
#pragma unroll
    for (int pp = 0; pp < PPT; pp++) {
        int p = tid + pp * NT;
        int s = p / NPIX; int pix = p - s * NPIX;
        int oy = pix / OW, ox = pix - oy * OW;
        if (UP) {
            int ry[3], cx[3];
#pragma unroll
            for (int k = 0; k < 3; k++) {
                ry[k] = ((oy - 1 + k) >> 1) + 1;
                cx[k] = ((ox - 1 + k) >> 1) + 1;
            }
#pragma unroll
            for (int ky = 0; ky < 3; ky++)
#pragma unroll
                for (int kx = 0; kx < 3; kx++) off[pp][ky*3+kx] = ry[ky] * PW_ + cx[kx];
        } else {
            off[pp][0] = oy * STRIDE * PW_ + ox * STRIDE;
        }
        sbase[pp] = s * CI_T * PA;
        sArr[pp] = s; pixArr[pp] = pix;
    }

    ull acc[PPT][CO2];
#pragma unroll
    for (int pp = 0; pp < PPT; pp++)
#pragma unroll
        for (int c2 = 0; c2 < CO2; c2++) acc[pp][c2] = 0ull;

    for (int ci0 = 0; ci0 < CIN; ci0 += CI_T) {
        __syncthreads();   // orders weight staging (first iter) / prior compute
        for (int i = tid; i < SB * CI_T * PA; i += NT) {
            int s = i / (CI_T * PA); int r = i - s * CI_T * PA;
            int ci = r / PA; int q = r - ci * PA;
            int py = q / PW_, px = q - py * PW_;
            int iy = py - 1, ix = px - 1;
            float v = 0.f;
            if (iy >= 0 && iy < SH && ix >= 0 && ix < SW_)
                v = in[(((size_t)(nb + s) * CIN + ci0 + ci) * SH + iy) * SW_ + ix];
            sp[i] = v;
        }
        __syncthreads();
#pragma unroll 1
        for (int ci = 0; ci < CI_T; ci++) {
            const ull* wrow = sw2 + (size_t)((ci0 + ci) * 9) * CO2;
#pragma unroll
            for (int t = 0; t < 9; t++) {
                constexpr int DDY[9] = {0,0,0,1,1,1,2,2,2};
                constexpr int DDX[9] = {0,1,2,0,1,2,0,1,2};
                ull v2[PPT];
#pragma unroll
                for (int pp = 0; pp < PPT; pp++) {
                    const float* cb = sp + sbase[pp] + ci * PA;
                    float tv = UP ? cb[off[pp][t]]
                                  : cb[off[pp][0] + DDY[t] * PW_ + DDX[t]];
                    v2[pp] = dup2(tv);
                }
                const ull* wt_ = wrow + t * CO2;
#pragma unroll
                for (int c2 = 0; c2 < CO2; c2++) {
                    ull wv = wt_[c2];
#pragma unroll
                    for (int pp = 0; pp < PPT; pp++) fma2(acc[pp][c2], v2[pp], wv);
                }
            }
        }
    }

    // epilogue
#pragma unroll
    for (int pp = 0; pp < PPT; pp++) {
        int n = nb + sArr[pp]; int pix = pixArr[pp];
#pragma unroll
        for (int c2 = 0; c2 < CO2; c2++) {
            float2 f = unpack2(acc[pp][c2]);
            int c0 = cob * CO_B + 2 * c2;
            float r0 = f.x + sbias[2*c2];
            float r1 = f.y + sbias[2*c2+1];
            if (ACT == 0)      { r0 = fmaxf(r0, 0.f); r1 = fmaxf(r1, 0.f); }
            else if (ACT == 1) { r0 = r0 > 0.f ? r0 : expm1f(r0); r1 = r1 > 0.f ? r1 : expm1f(r1); }
            else               { r0 = 1.f/(1.f+expf(-r0)); r1 = 1.f/(1.f+expf(-r1)); }
            out[((size_t)n * COUT + c0) * NPIX + pix] = r0;
            out[((size_t)n * COUT + c0 + 1) * NPIX + pix] = r1;
        }
    }
}

// ---------------- fused mu+logvar fc: [2048,6272] x 2x[6272,64], split-K=7 ----------------
__global__ void __launch_bounds__(256)
k_fc2(const float* __restrict__ A,
      const float* __restrict__ Wm, const float* __restrict__ bm,
      const float* __restrict__ Wl, const float* __restrict__ bl,
      float* __restrict__ Om, float* __restrict__ Ol) {
    __shared__ float sa[32][33];
    __shared__ float swm[32][64];
    __shared__ float swl[32][64];
    int tid = threadIdx.x, tx = tid & 15, ty = tid >> 4;
    float am[2][4] = {}, al[2][4] = {};
    int row0 = blockIdx.x * 32;
    int k0 = blockIdx.y * 896;
    for (int it = 0; it < 28; it++) {
        int kb = k0 + it * 32;
        for (int i = tid; i < 32*32; i += 256) { int r = i>>5, c = i&31; sa[r][c] = A[(size_t)(row0+r)*6272 + kb + c]; }
        for (int i = tid; i < 32*64; i += 256) { int r = i>>6, c = i&63;
            swm[r][c] = Wm[(size_t)(kb+r)*64 + c];
            swl[r][c] = Wl[(size_t)(kb+r)*64 + c]; }
        __syncthreads();
#pragma unroll
        for (int kk = 0; kk < 32; kk++) {
            float a0 = sa[ty*2][kk], a1 = sa[ty*2+1][kk];
#pragma unroll
            for (int j = 0; j < 4; j++) {
                float wm_ = swm[kk][tx*4+j], wl_ = swl[kk][tx*4+j];
                am[0][j] += a0 * wm_; am[1][j] += a1 * wm_;
                al[0][j] += a0 * wl_; al[1][j] += a1 * wl_;
            }
        }
        __syncthreads();
    }
#pragma unroll
    for (int i = 0; i < 2; i++)
#pragma unroll
        for (int j = 0; j < 4; j++) {
            int r = row0 + ty*2 + i, c = tx*4 + j;
            float vm = am[i][j], vl = al[i][j];
            if (blockIdx.y == 0) { vm += bm[c]; vl += bl[c]; }
            atomicAdd(&Om[(size_t)r*64 + c], vm);
            atomicAdd(&Ol[(size_t)r*64 + c], vl);
        }
}

// ---------------- z sample + gating MLP + softmax + argmax ----------------
__global__ void __launch_bounds__(64)
k_gate(const float* __restrict__ mu, const float* __restrict__ lv, const float* __restrict__ eps,
       const float* __restrict__ w1, const float* __restrict__ b1,
       const float* __restrict__ w2, const float* __restrict__ b2,
       const float* __restrict__ w3, const float* __restrict__ b3,
       float* __restrict__ logits_out, float* __restrict__ probs_out) {
    int n = blockIdx.x, t = threadIdx.x;
    __shared__ float zz[64], h1[64], h2[32], lg[8];
    float m = mu[(size_t)n*64 + t], l = lv[(size_t)n*64 + t];
    float z = m + eps[(size_t)n*64 + t] * expf(0.5f * l);
    zz[t] = z;
    g_z[(size_t)n*64 + t] = z;
    __syncthreads();
    float a = b1[t];
    for (int k = 0; k < 64; k++) a += zz[k] * w1[k*64 + t];
    h1[t] = fmaxf(a, 0.f);
    __syncthreads();
    if (t < 32) {
        float a2 = b2[t];
        for (int k = 0; k < 64; k++) a2 += h1[k] * w2[k*32 + t];
        h2[t] = fmaxf(a2, 0.f);
    }
    __syncthreads();
    if (t < 8) {
        float a3 = b3[t];
        for (int k = 0; k < 32; k++) a3 += h2[k] * w3[k*8 + t];
        lg[t] = a3;
    }
    __syncthreads();
    if (t == 0) {
        float mx = lg[0];
        for (int i = 1; i < 8; i++) mx = fmaxf(mx, lg[i]);
        float e[8], s = 0.f;
        for (int i = 0; i < 8; i++) { e[i] = expf(lg[i] - mx); s += e[i]; }
        float inv = 1.f / s;
        int best = 0; float bp = -1.f;
        for (int i = 0; i < 8; i++) {
            float p = e[i] * inv;
            probs_out[(size_t)n*8 + i] = p;
            logits_out[(size_t)n*8 + i] = logf(p + 1e-8f);
            if (p > bp) { bp = p; best = i; }
        }
        g_eidx[n] = best;
    }
}

// ---------------- decoder fc (selected expert) ----------------
__global__ void __launch_bounds__(256)
k_dec_fc(const float* __restrict__ fcw, const float* __restrict__ fcb) {
    int n = blockIdx.x, t = threadIdx.x;
    __shared__ float zz[64];
    int e = g_eidx[n];
    if (t < 64) zz[t] = g_z[(size_t)n*64 + t];
    __syncthreads();
    const float* W = fcw + (size_t)e * 64 * 1568;
    const float* B = fcb + (size_t)e * 1568;
    for (int o = t; o < 1568; o += 256) {
        float a = B[o];
#pragma unroll 8
        for (int k = 0; k < 64; k++) a += zz[k] * W[(size_t)k*1568 + o];
        g_dfc[(size_t)n*1568 + o] = a;
    }
}

// ---------------- decoder conv3 (32->1, sigmoid) ----------------
__global__ void __launch_bounds__(196)
k_dconv3(const float* __restrict__ in, const float* __restrict__ wt,
         const float* __restrict__ bs, float* __restrict__ out, const int* __restrict__ eidx) {
    extern __shared__ float sp3[];   // 32*900
    __shared__ float sw[288];
    __shared__ float sb0;
    int n = blockIdx.x, tid = threadIdx.x;
    int e = eidx[n];
    const float* wb = wt + (size_t)e * 288;
    if (tid == 0) sb0 = bs[e];
    for (int i = tid; i < 288; i += 196) sw[i] = wb[i];
    const float* inn = in + (size_t)n * 32 * 784;
    for (int i = tid; i < 32*900; i += 196) {
        int ci = i / 900, q = i - ci*900;
        int py = q / 30, px = q - py*30;
        int iy = py - 1, ix = px - 1;
        float v = 0.f;
        if (iy >= 0 && iy < 28 && ix >= 0 && ix < 28) v = inn[ci*784 + iy*28 + ix];
        sp3[i] = v;
    }
    __syncthreads();
    int base[4]; int pixA[4];
#pragma unroll
    for (int pp = 0; pp < 4; pp++) {
        int p = tid + pp*196; pixA[pp] = p;
        int oy = p / 28, ox = p - oy*28;
        base[pp] = oy*30 + ox;
    }
    float acc[4] = {0.f, 0.f, 0.f, 0.f};
    for (int ci = 0; ci < 32; ci++) {
        float wr[9];
#pragma unroll
        for (int t = 0; t < 9; t++) wr[t] = sw[ci*9 + t];
        const float* cb = sp3 + ci*900;
#pragma unroll
        for (int ky = 0; ky < 3; ky++)
#pragma unroll
            for (int kx = 0; kx < 3; kx++) {
#pragma unroll
                for (int pp = 0; pp < 4; pp++)
                    acc[pp] += cb[base[pp] + ky*30 + kx] * wr[ky*3+kx];
            }
    }
#pragma unroll
    for (int pp = 0; pp < 4; pp++) {
        float r = acc[pp] + sb0;
        out[(size_t)n*784 + pixA[pp]] = 1.f / (1.f + expf(-r));
    }
}

// ---------------- launcher ----------------
extern "C" void kernel_launch(void* const* d_in, const int* in_sizes, int n_in,
                              void* d_out, int out_size) {
    const float* x      = (const float*)d_in[0];
    const float* eps    = (const float*)d_in[1];
    const float* enc_w1 = (const float*)d_in[2];  const float* enc_b1 = (const float*)d_in[3];
    const float* enc_w2 = (const float*)d_in[4];  const float* enc_b2 = (const float*)d_in[5];
    const float* enc_w3 = (const float*)d_in[6];  const float* enc_b3 = (const float*)d_in[7];
    const float* w_mu   = (const float*)d_in[8];  const float* b_mu   = (const float*)d_in[9];
    const float* w_lv   = (const float*)d_in[10]; const float* b_lv   = (const float*)d_in[11];
    const float* g_w1   = (const float*)d_in[12]; const float* g_b1   = (const float*)d_in[13];
    const float* g_w2   = (const float*)d_in[14]; const float* g_b2   = (const float*)d_in[15];
    const float* g_w3   = (const float*)d_in[16]; const float* g_b3   = (const float*)d_in[17];
    const float* d_fc_w = (const float*)d_in[18]; const float* d_fc_b = (const float*)d_in[19];
    const float* d_w1   = (const float*)d_in[20]; const float* d_b1   = (const float*)d_in[21];
    const float* d_w2   = (const float*)d_in[22]; const float* d_b2   = (const float*)d_in[23];
    const float* d_w3   = (const float*)d_in[24]; const float* d_b3   = (const float*)d_in[25];

    float* out   = (float*)d_out;
    float* o_rec = out;
    float* o_mu  = out + (size_t)BB*784;
    float* o_lv  = o_mu + (size_t)BB*64;
    float* o_lg  = o_lv + (size_t)BB*64;
    float* o_pb  = o_lg + (size_t)BB*8;

    float *h1, *h2, *h3, *dfc, *dh1, *dh2; int* eidx;
    cudaGetSymbolAddress((void**)&h1,  g_h1);
    cudaGetSymbolAddress((void**)&h2,  g_h2);
    cudaGetSymbolAddress((void**)&h3,  g_h3);
    cudaGetSymbolAddress((void**)&dfc, g_dfc);
    cudaGetSymbolAddress((void**)&dh1, g_dh1);
    cudaGetSymbolAddress((void**)&dh2, g_dh2);
    cudaGetSymbolAddress((void**)&eidx, g_eidx);

    // enc2: 32->64, 28x28 s2 -> 14x14; SB=4, CI_T=4
    auto enc2 = conv3k<32,64,16, 14,14, 28,28, 2,0,0, 196,4,4,4,2>;
    constexpr int SM_ENC2 = 4*4*900*4 + 32*9*8*8;            // 57600+18432=76032
    // enc3: 64->128, 14x14 s2 -> 7x7; SB=16, CI_T=4
    auto enc3 = conv3k<64,128,16, 7,7, 14,14, 2,0,0, 196,4,16,4,2>;
    constexpr int SM_ENC3 = 16*4*256*4 + 64*9*8*8;           // 65536+36864=102400
    // dec1: 32->64, up 7->14; SB=1, 49 threads
    auto dec1 = conv3k<32,64,16, 14,14, 7,7, 1,1,1, 49,4,1,32,2>;
    constexpr int SM_DEC1 = 32*81*4 + 32*9*8*8;              // 10368+18432=28800
    // dec2: 64->32, up 14->28; SB=1, stage-once
    auto dec2 = conv3k<64,32,16, 28,28, 14,14, 1,1,1, 196,4,1,64,2>;
    constexpr int SM_DEC2 = 64*256*4 + 64*9*8*8;             // 65536+36864=102400
    constexpr int SM_DEC3 = 32*900*4;                         // 115200

    cudaFuncSetAttribute(enc2, cudaFuncAttributeMaxDynamicSharedMemorySize, SM_ENC2);
    cudaFuncSetAttribute(enc3, cudaFuncAttributeMaxDynamicSharedMemorySize, SM_ENC3);
    cudaFuncSetAttribute(dec1, cudaFuncAttributeMaxDynamicSharedMemorySize, SM_DEC1);
    cudaFuncSetAttribute(dec2, cudaFuncAttributeMaxDynamicSharedMemorySize, SM_DEC2);
    cudaFuncSetAttribute(k_dconv3, cudaFuncAttributeMaxDynamicSharedMemorySize, SM_DEC3);

    // mu/lv accumulated with atomics -> zero first
    cudaMemsetAsync(o_mu, 0, (size_t)BB*128*sizeof(float));

    // encoder
    k_enc_conv1<<<BB, 256>>>(x, enc_w1, enc_b1, h1);
    enc2<<<dim3(BB/4, 4),   196, SM_ENC2>>>(h1, enc_w2, enc_b2, h2, nullptr);
    enc3<<<dim3(BB/16, 8),  196, SM_ENC3>>>(h2, enc_w3, enc_b3, h3, nullptr);

    // mu / log_var fused
    k_fc2<<<dim3(64, 7), 256>>>(h3, w_mu, b_mu, w_lv, b_lv, o_mu, o_lv);

    // gating + expert selection
    k_gate<<<BB, 64>>>(o_mu, o_lv, eps, g_w1, g_b1, g_w2, g_b2, g_w3, g_b3, o_lg, o_pb);

    // decoder: only the selected expert per sample
    k_dec_fc<<<BB, 256>>>(d_fc_w, d_fc_b);
    dec1<<<dim3(BB, 4),  49, SM_DEC1>>>(dfc, d_w1, d_b1, dh1, eidx);
    dec2<<<dim3(BB, 2), 196, SM_DEC2>>>(dh1, d_w2, d_b2, dh2, eidx);
    k_dconv3<<<BB, 196, SM_DEC3>>>(dh2, d_w3, d_b3, o_rec, eidx);
}

// round 6
// speedup vs baseline: 1.3656x; 1.0193x over previous
#include <cuda_runtime.h>
#include <math.h>
#include <stdint.h>

#define BB 2048
typedef unsigned long long ull;

// ---------------- f32x2 packed-math helpers ----------------
__device__ __forceinline__ ull dup2(float v) {
    unsigned x = __float_as_uint(v); ull r;
    asm("mov.b64 %0, {%1, %1};" : "=l"(r) : "r"(x));
    return r;
}
__device__ __forceinline__ ull pack2(float a, float b) {
    unsigned x = __float_as_uint(a), y = __float_as_uint(b); ull r;
    asm("mov.b64 %0, {%1, %2};" : "=l"(r) : "r"(x), "r"(y));
    return r;
}
__device__ __forceinline__ void fma2(ull& d, ull a, ull b) {
    asm("fma.rn.f32x2 %0, %1, %2, %0;" : "+l"(d) : "l"(a), "l"(b));
}
__device__ __forceinline__ float2 unpack2(ull v) {
    unsigned x, y;
    asm("mov.b64 {%0, %1}, %2;" : "=r"(x), "=r"(y) : "l"(v));
    float2 f; f.x = __uint_as_float(x); f.y = __uint_as_float(y); return f;
}

// ---------------- scratch (device globals) ----------------
__device__ float g_h1[(size_t)BB*32*28*28];
__device__ float g_h2[(size_t)BB*64*14*14];
__device__ float g_h3[(size_t)BB*128*7*7];
__device__ float g_z [(size_t)BB*64];
__device__ int   g_eidx[BB];
__device__ float g_dfc[(size_t)BB*32*7*7];
__device__ float g_dh1[(size_t)BB*64*14*14];
__device__ float g_dh2[(size_t)BB*32*28*28];

// ---------------- encoder conv1 (1->32, 28x28, relu) ----------------
__global__ void k_enc_conv1(const float* __restrict__ x, const float* __restrict__ w,
                            const float* __restrict__ b, float* __restrict__ out) {
    __shared__ float sin_[784];
    __shared__ float sw[288];
    __shared__ float sb[32];
    int n = blockIdx.x, tid = threadIdx.x;
    const float* xin = x + (size_t)n * 784;
    for (int i = tid; i < 784; i += 256) sin_[i] = xin[i];
    for (int i = tid; i < 288; i += 256) sw[i] = w[i];
    if (tid < 32) sb[tid] = b[tid];
    __syncthreads();
    for (int p = tid; p < 784; p += 256) {
        int oy = p / 28, ox = p % 28;
        float v[9];
#pragma unroll
        for (int ky = 0; ky < 3; ky++)
#pragma unroll
            for (int kx = 0; kx < 3; kx++) {
                int iy = oy - 1 + ky, ix = ox - 1 + kx;
                v[ky*3+kx] = (iy >= 0 && iy < 28 && ix >= 0 && ix < 28) ? sin_[iy*28+ix] : 0.f;
            }
        for (int co = 0; co < 32; co++) {
            float a = sb[co];
#pragma unroll
            for (int t = 0; t < 9; t++) a += v[t] * sw[co*9+t];
            out[((size_t)n*32 + co)*784 + p] = fmaxf(a, 0.f);
        }
    }
}

// ---------------- f32x2 cout-pair conv; UP taps deduped to 4 loads ------
// ACT: 0=relu 1=elu 2=sigmoid
template<int CIN,int COUT,int CO_B,int OH,int OW,int SH,int SW_,int STRIDE,int UP,int ACT,
         int NT,int PPT,int SB,int CI_T,int MINB>
__global__ void __launch_bounds__(NT, MINB)
conv3k(const float* __restrict__ in, const float* __restrict__ wt,
       const float* __restrict__ bs, float* __restrict__ out, const int* __restrict__ eidx) {
    constexpr int PW_ = SW_ + 2, PH_ = SH + 2, PA = PW_ * PH_;
    constexpr int NPIX = OH * OW, CO2 = CO_B / 2;
    static_assert(NT * PPT == SB * NPIX, "coverage");
    static_assert(CIN % CI_T == 0, "citile");
    static_assert(((SB * CI_T * PA) & 1) == 0, "align8");

    extern __shared__ ull dsm[];
    float* sp = (float*)dsm;
    ull* sw2 = dsm + (size_t)(SB * CI_T * PA) / 2;
    __shared__ float sbias[CO_B];

    const int tid = threadIdx.x;
    const int nb = blockIdx.x * SB;
    const int cob = blockIdx.y;
    const float* wb = wt;
    const float* bb = bs;
    if (eidx) { int e = eidx[nb]; wb += (size_t)e * COUT * CIN * 9; bb += (size_t)e * COUT; }

    // stage packed weights ONCE: sw2[(ci*9+t)*CO2 + c2]
    for (int i = tid; i < CIN * 9 * CO2; i += NT) {
        int ci = i / (9 * CO2); int r = i - ci * 9 * CO2;
        int t = r / CO2; int c2 = r - t * CO2;
        int c0 = cob * CO_B + 2 * c2;
        float w0 = wb[((size_t)c0 * CIN + ci) * 9 + t];
        float w1 = wb[((size_t)(c0 + 1) * CIN + ci) * 9 + t];
        sw2[(ci * 9 + t) * CO2 + c2] = pack2(w0, w1);
    }
    if (tid < CO_B) sbias[tid] = bb[cob * CO_B + tid];

    // per-thread pixel setup
    int aoff[PPT];            // UP: base addr of AA tap; strided: base corner
    bool pyA[PPT], pxA[PPT];  // UP parity: true -> middle row/col selects "A"
    int sbase[PPT]; int sArr[PPT]; int pixArr[PPT];
#pragma unroll
    for (int pp = 0; pp < PPT; pp++) {
        int p = tid + pp * NT;
        int s = p / NPIX; int pix = p - s * NPIX;
        int oy = pix / OW, ox = pix - oy * OW;
        if (UP) {
            int rA = ((oy - 1) >> 1) + 1;
            int cA = ((ox - 1) >> 1) + 1;
            aoff[pp] = rA * PW_ + cA;
            pyA[pp] = (oy & 1) != 0;
            pxA[pp] = (ox & 1) != 0;
        } else {
            aoff[pp] = oy * STRIDE * PW_ + ox * STRIDE;
        }
        sbase[pp] = s * CI_T * PA;
        sArr[pp] = s; pixArr[pp] = pix;
    }

    ull acc[PPT][CO2];
#pragma unroll
    for (int pp = 0; pp < PPT; pp++)
#pragma unroll
        for (int c2 = 0; c2 < CO2; c2++) acc[pp][c2] = 0ull;

    for (int ci0 = 0; ci0 < CIN; ci0 += CI_T) {
        __syncthreads();
        for (int i = tid; i < SB * CI_T * PA; i += NT) {
            int s = i / (CI_T * PA); int r = i - s * CI_T * PA;
            int ci = r / PA; int q = r - ci * PA;
            int py = q / PW_, px = q - py * PW_;
            int iy = py - 1, ix = px - 1;
            float v = 0.f;
            if (iy >= 0 && iy < SH && ix >= 0 && ix < SW_)
                v = in[(((size_t)(nb + s) * CIN + ci0 + ci) * SH + iy) * SW_ + ix];
            sp[i] = v;
        }
        __syncthreads();
#pragma unroll 1
        for (int ci = 0; ci < CI_T; ci++) {
            const ull* wrow = sw2 + (size_t)((ci0 + ci) * 9) * CO2;
            // UP: 4 deduped tap loads per pp (immediate offsets from one base)
            ull uAA[PPT], uAB[PPT], uBA[PPT], uBB[PPT];
            if (UP) {
#pragma unroll
                for (int pp = 0; pp < PPT; pp++) {
                    const float* cb = sp + sbase[pp] + ci * PA + aoff[pp];
                    uAA[pp] = dup2(cb[0]);
                    uAB[pp] = dup2(cb[1]);
                    uBA[pp] = dup2(cb[PW_]);
                    uBB[pp] = dup2(cb[PW_ + 1]);
                }
            }
#pragma unroll
            for (int t = 0; t < 9; t++) {
                constexpr int DDY[9] = {0,0,0,1,1,1,2,2,2};
                constexpr int DDX[9] = {0,1,2,0,1,2,0,1,2};
                ull v2[PPT];
#pragma unroll
                for (int pp = 0; pp < PPT; pp++) {
                    if (UP) {
                        ull a = uAA[pp], b = uAB[pp], c = uBA[pp], d = uBB[pp];
                        bool py = pyA[pp], px = pxA[pp];
                        ull tv;
                        if      (t == 0) tv = a;
                        else if (t == 1) tv = px ? a : b;
                        else if (t == 2) tv = b;
                        else if (t == 3) tv = py ? a : c;
                        else if (t == 4) tv = py ? (px ? a : b) : (px ? c : d);
                        else if (t == 5) tv = py ? b : d;
                        else if (t == 6) tv = c;
                        else if (t == 7) tv = px ? c : d;
                        else             tv = d;
                        v2[pp] = tv;
                    } else {
                        const float* cb = sp + sbase[pp] + ci * PA;
                        v2[pp] = dup2(cb[aoff[pp] + DDY[t] * PW_ + DDX[t]]);
                    }
                }
                const ull* wt_ = wrow + t * CO2;
#pragma unroll
                for (int c2 = 0; c2 < CO2; c2++) {
                    ull wv = wt_[c2];
#pragma unroll
                    for (int pp = 0; pp < PPT; pp++) fma2(acc[pp][c2], v2[pp], wv);
                }
            }
        }
    }

    // epilogue
#pragma unroll
    for (int pp = 0; pp < PPT; pp++) {
        int n = nb + sArr[pp]; int pix = pixArr[pp];
#pragma unroll
        for (int c2 = 0; c2 < CO2; c2++) {
            float2 f = unpack2(acc[pp][c2]);
            int c0 = cob * CO_B + 2 * c2;
            float r0 = f.x + sbias[2*c2];
            float r1 = f.y + sbias[2*c2+1];
            if (ACT == 0)      { r0 = fmaxf(r0, 0.f); r1 = fmaxf(r1, 0.f); }
            else if (ACT == 1) { r0 = r0 > 0.f ? r0 : expm1f(r0); r1 = r1 > 0.f ? r1 : expm1f(r1); }
            else               { r0 = 1.f/(1.f+expf(-r0)); r1 = 1.f/(1.f+expf(-r1)); }
            out[((size_t)n * COUT + c0) * NPIX + pix] = r0;
            out[((size_t)n * COUT + c0 + 1) * NPIX + pix] = r1;
        }
    }
}

// ---------------- fused mu+logvar fc ----------------
__global__ void __launch_bounds__(256)
k_fc2(const float* __restrict__ A,
      const float* __restrict__ Wm, const float* __restrict__ bm,
      const float* __restrict__ Wl, const float* __restrict__ bl,
      float* __restrict__ Om, float* __restrict__ Ol) {
    __shared__ float sa[32][33];
    __shared__ float swm[32][64];
    __shared__ float swl[32][64];
    int tid = threadIdx.x, tx = tid & 15, ty = tid >> 4;
    float am[2][4] = {}, al[2][4] = {};
    int row0 = blockIdx.x * 32;
    int k0 = blockIdx.y * 896;
    for (int it = 0; it < 28; it++) {
        int kb = k0 + it * 32;
        for (int i = tid; i < 32*32; i += 256) { int r = i>>5, c = i&31; sa[r][c] = A[(size_t)(row0+r)*6272 + kb + c]; }
        for (int i = tid; i < 32*64; i += 256) { int r = i>>6, c = i&63;
            swm[r][c] = Wm[(size_t)(kb+r)*64 + c];
            swl[r][c] = Wl[(size_t)(kb+r)*64 + c]; }
        __syncthreads();
#pragma unroll
        for (int kk = 0; kk < 32; kk++) {
            float a0 = sa[ty*2][kk], a1 = sa[ty*2+1][kk];
#pragma unroll
            for (int j = 0; j < 4; j++) {
                float wm_ = swm[kk][tx*4+j], wl_ = swl[kk][tx*4+j];
                am[0][j] += a0 * wm_; am[1][j] += a1 * wm_;
                al[0][j] += a0 * wl_; al[1][j] += a1 * wl_;
            }
        }
        __syncthreads();
    }
#pragma unroll
    for (int i = 0; i < 2; i++)
#pragma unroll
        for (int j = 0; j < 4; j++) {
            int r = row0 + ty*2 + i, c = tx*4 + j;
            float vm = am[i][j], vl = al[i][j];
            if (blockIdx.y == 0) { vm += bm[c]; vl += bl[c]; }
            atomicAdd(&Om[(size_t)r*64 + c], vm);
            atomicAdd(&Ol[(size_t)r*64 + c], vl);
        }
}

// ---------------- z sample + gating MLP + softmax + argmax ----------------
__global__ void __launch_bounds__(64)
k_gate(const float* __restrict__ mu, const float* __restrict__ lv, const float* __restrict__ eps,
       const float* __restrict__ w1, const float* __restrict__ b1,
       const float* __restrict__ w2, const float* __restrict__ b2,
       const float* __restrict__ w3, const float* __restrict__ b3,
       float* __restrict__ logits_out, float* __restrict__ probs_out) {
    int n = blockIdx.x, t = threadIdx.x;
    __shared__ float zz[64], h1[64], h2[32], lg[8];
    float m = mu[(size_t)n*64 + t], l = lv[(size_t)n*64 + t];
    float z = m + eps[(size_t)n*64 + t] * expf(0.5f * l);
    zz[t] = z;
    g_z[(size_t)n*64 + t] = z;
    __syncthreads();
    float a = b1[t];
    for (int k = 0; k < 64; k++) a += zz[k] * w1[k*64 + t];
    h1[t] = fmaxf(a, 0.f);
    __syncthreads();
    if (t < 32) {
        float a2 = b2[t];
        for (int k = 0; k < 64; k++) a2 += h1[k] * w2[k*32 + t];
        h2[t] = fmaxf(a2, 0.f);
    }
    __syncthreads();
    if (t < 8) {
        float a3 = b3[t];
        for (int k = 0; k < 32; k++) a3 += h2[k] * w3[k*8 + t];
        lg[t] = a3;
    }
    __syncthreads();
    if (t == 0) {
        float mx = lg[0];
        for (int i = 1; i < 8; i++) mx = fmaxf(mx, lg[i]);
        float e[8], s = 0.f;
        for (int i = 0; i < 8; i++) { e[i] = expf(lg[i] - mx); s += e[i]; }
        float inv = 1.f / s;
        int best = 0; float bp = -1.f;
        for (int i = 0; i < 8; i++) {
            float p = e[i] * inv;
            probs_out[(size_t)n*8 + i] = p;
            logits_out[(size_t)n*8 + i] = logf(p + 1e-8f);
            if (p > bp) { bp = p; best = i; }
        }
        g_eidx[n] = best;
    }
}

// ---------------- decoder fc (selected expert) ----------------
__global__ void __launch_bounds__(256)
k_dec_fc(const float* __restrict__ fcw, const float* __restrict__ fcb) {
    int n = blockIdx.x, t = threadIdx.x;
    __shared__ float zz[64];
    int e = g_eidx[n];
    if (t < 64) zz[t] = g_z[(size_t)n*64 + t];
    __syncthreads();
    const float* W = fcw + (size_t)e * 64 * 1568;
    const float* B = fcb + (size_t)e * 1568;
    for (int o = t; o < 1568; o += 256) {
        float a = B[o];
#pragma unroll 8
        for (int k = 0; k < 64; k++) a += zz[k] * W[(size_t)k*1568 + o];
        g_dfc[(size_t)n*1568 + o] = a;
    }
}

// ---------------- decoder conv3 (32->1, sigmoid) ----------------
__global__ void __launch_bounds__(196)
k_dconv3(const float* __restrict__ in, const float* __restrict__ wt,
         const float* __restrict__ bs, float* __restrict__ out, const int* __restrict__ eidx) {
    extern __shared__ float sp3[];   // 32*900
    __shared__ float sw[288];
    __shared__ float sb0;
    int n = blockIdx.x, tid = threadIdx.x;
    int e = eidx[n];
    const float* wb = wt + (size_t)e * 288;
    if (tid == 0) sb0 = bs[e];
    for (int i = tid; i < 288; i += 196) sw[i] = wb[i];
    const float* inn = in + (size_t)n * 32 * 784;
    for (int i = tid; i < 32*900; i += 196) {
        int ci = i / 900, q = i - ci*900;
        int py = q / 30, px = q - py*30;
        int iy = py - 1, ix = px - 1;
        float v = 0.f;
        if (iy >= 0 && iy < 28 && ix >= 0 && ix < 28) v = inn[ci*784 + iy*28 + ix];
        sp3[i] = v;
    }
    __syncthreads();
    int base[4]; int pixA[4];
#pragma unroll
    for (int pp = 0; pp < 4; pp++) {
        int p = tid + pp*196; pixA[pp] = p;
        int oy = p / 28, ox = p - oy*28;
        base[pp] = oy*30 + ox;
    }
    float acc[4] = {0.f, 0.f, 0.f, 0.f};
    for (int ci = 0; ci < 32; ci++) {
        float wr[9];
#pragma unroll
        for (int t = 0; t < 9; t++) wr[t] = sw[ci*9 + t];
        const float* cb = sp3 + ci*900;
#pragma unroll
        for (int ky = 0; ky < 3; ky++)
#pragma unroll
            for (int kx = 0; kx < 3; kx++) {
#pragma unroll
                for (int pp = 0; pp < 4; pp++)
                    acc[pp] += cb[base[pp] + ky*30 + kx] * wr[ky*3+kx];
            }
    }
#pragma unroll
    for (int pp = 0; pp < 4; pp++) {
        float r = acc[pp] + sb0;
        out[(size_t)n*784 + pixA[pp]] = 1.f / (1.f + expf(-r));
    }
}

// ---------------- launcher ----------------
extern "C" void kernel_launch(void* const* d_in, const int* in_sizes, int n_in,
                              void* d_out, int out_size) {
    const float* x      = (const float*)d_in[0];
    const float* eps    = (const float*)d_in[1];
    const float* enc_w1 = (const float*)d_in[2];  const float* enc_b1 = (const float*)d_in[3];
    const float* enc_w2 = (const float*)d_in[4];  const float* enc_b2 = (const float*)d_in[5];
    const float* enc_w3 = (const float*)d_in[6];  const float* enc_b3 = (const float*)d_in[7];
    const float* w_mu   = (const float*)d_in[8];  const float* b_mu   = (const float*)d_in[9];
    const float* w_lv   = (const float*)d_in[10]; const float* b_lv   = (const float*)d_in[11];
    const float* g_w1   = (const float*)d_in[12]; const float* g_b1   = (const float*)d_in[13];
    const float* g_w2   = (const float*)d_in[14]; const float* g_b2   = (const float*)d_in[15];
    const float* g_w3   = (const float*)d_in[16]; const float* g_b3   = (const float*)d_in[17];
    const float* d_fc_w = (const float*)d_in[18]; const float* d_fc_b = (const float*)d_in[19];
    const float* d_w1   = (const float*)d_in[20]; const float* d_b1   = (const float*)d_in[21];
    const float* d_w2   = (const float*)d_in[22]; const float* d_b2   = (const float*)d_in[23];
    const float* d_w3   = (const float*)d_in[24]; const float* d_b3   = (const float*)d_in[25];

    float* out   = (float*)d_out;
    float* o_rec = out;
    float* o_mu  = out + (size_t)BB*784;
    float* o_lv  = o_mu + (size_t)BB*64;
    float* o_lg  = o_lv + (size_t)BB*64;
    float* o_pb  = o_lg + (size_t)BB*8;

    float *h1, *h2, *h3, *dfc, *dh1, *dh2; int* eidx;
    cudaGetSymbolAddress((void**)&h1,  g_h1);
    cudaGetSymbolAddress((void**)&h2,  g_h2);
    cudaGetSymbolAddress((void**)&h3,  g_h3);
    cudaGetSymbolAddress((void**)&dfc, g_dfc);
    cudaGetSymbolAddress((void**)&dh1, g_dh1);
    cudaGetSymbolAddress((void**)&dh2, g_dh2);
    cudaGetSymbolAddress((void**)&eidx, g_eidx);

    // enc2: 32->64, 28->14 s2; SB=4, CI_T=2
    auto enc2 = conv3k<32,64,16, 14,14, 28,28, 2,0,0, 196,4,4,2,3>;
    constexpr int SM_ENC2 = 4*2*900*4 + 32*9*8*8;            // 28800+18432=47232
    // enc3: 64->128, 14->7 s2; SB=16, CI_T=2
    auto enc3 = conv3k<64,128,16, 7,7, 14,14, 2,0,0, 196,4,16,2,3>;
    constexpr int SM_ENC3 = 16*2*256*4 + 64*9*8*8;           // 32768+36864=69632
    // dec1: 32->64, up 7->14; SB=1, NT=98, PPT=2
    auto dec1 = conv3k<32,64,16, 14,14, 7,7, 1,1,1, 98,2,1,32,5>;
    constexpr int SM_DEC1 = 32*81*4 + 32*9*8*8;              // 10368+18432=28800
    // dec2: 64->32, up 14->28; SB=1, CI_T=32
    auto dec2 = conv3k<64,32,16, 28,28, 14,14, 1,1,1, 196,4,1,32,2>;
    constexpr int SM_DEC2 = 32*256*4 + 64*9*8*8;             // 32768+36864=69632
    constexpr int SM_DEC3 = 32*900*4;                         // 115200

    cudaFuncSetAttribute(enc2, cudaFuncAttributeMaxDynamicSharedMemorySize, SM_ENC2);
    cudaFuncSetAttribute(enc3, cudaFuncAttributeMaxDynamicSharedMemorySize, SM_ENC3);
    cudaFuncSetAttribute(dec1, cudaFuncAttributeMaxDynamicSharedMemorySize, SM_DEC1);
    cudaFuncSetAttribute(dec2, cudaFuncAttributeMaxDynamicSharedMemorySize, SM_DEC2);
    cudaFuncSetAttribute(k_dconv3, cudaFuncAttributeMaxDynamicSharedMemorySize, SM_DEC3);

    cudaMemsetAsync(o_mu, 0, (size_t)BB*128*sizeof(float));

    // encoder
    k_enc_conv1<<<BB, 256>>>(x, enc_w1, enc_b1, h1);
    enc2<<<dim3(BB/4, 4),   196, SM_ENC2>>>(h1, enc_w2, enc_b2, h2, nullptr);
    enc3<<<dim3(BB/16, 8),  196, SM_ENC3>>>(h2, enc_w3, enc_b3, h3, nullptr);

    // mu / log_var fused
    k_fc2<<<dim3(64, 7), 256>>>(h3, w_mu, b_mu, w_lv, b_lv, o_mu, o_lv);

    // gating + expert selection
    k_gate<<<BB, 64>>>(o_mu, o_lv, eps, g_w1, g_b1, g_w2, g_b2, g_w3, g_b3, o_lg, o_pb);

    // decoder: only the selected expert per sample
    k_dec_fc<<<BB, 256>>>(d_fc_w, d_fc_b);
    dec1<<<dim3(BB, 4),  98, SM_DEC1>>>(dfc, d_w1, d_b1, dh1, eidx);
    dec2<<<dim3(BB, 2), 196, SM_DEC2>>>(dh1, d_w2, d_b2, dh2, eidx);
    k_dconv3<<<BB, 196, SM_DEC3>>>(dh2, d_w3, d_b3, o_rec, eidx);
}

// round 7
// speedup vs baseline: 1.7067x; 1.2498x over previous
#include <cuda_runtime.h>
#include <math.h>
#include <stdint.h>

#define BB 2048
typedef unsigned long long ull;

// ---------------- f32x2 packed-math helpers ----------------
__device__ __forceinline__ ull dup2(float v) {
    unsigned x = __float_as_uint(v); ull r;
    asm("mov.b64 %0, {%1, %1};" : "=l"(r) : "r"(x));
    return r;
}
__device__ __forceinline__ ull pack2(float a, float b) {
    unsigned x = __float_as_uint(a), y = __float_as_uint(b); ull r;
    asm("mov.b64 %0, {%1, %2};" : "=l"(r) : "r"(x), "r"(y));
    return r;
}
__device__ __forceinline__ void fma2(ull& d, ull a, ull b) {
    asm("fma.rn.f32x2 %0, %1, %2, %0;" : "+l"(d) : "l"(a), "l"(b));
}
__device__ __forceinline__ float2 unpack2(ull v) {
    unsigned x, y;
    asm("mov.b64 {%0, %1}, %2;" : "=r"(x), "=r"(y) : "l"(v));
    float2 f; f.x = __uint_as_float(x); f.y = __uint_as_float(y); return f;
}
// ---------------- cp.async helpers ----------------
__device__ __forceinline__ void cpa4(uint32_t smem, const void* g, unsigned nbytes) {
    asm volatile("cp.async.ca.shared.global [%0], [%1], 4, %2;"
                 :: "r"(smem), "l"(g), "r"(nbytes));
}
__device__ __forceinline__ void cpa_commit() {
    asm volatile("cp.async.commit_group;" ::: "memory");
}
template<int N> __device__ __forceinline__ void cpa_wait() {
    asm volatile("cp.async.wait_group %0;" :: "n"(N) : "memory");
}

// ---------------- scratch (device globals) ----------------
__device__ float g_h1[(size_t)BB*32*28*28];
__device__ float g_h2[(size_t)BB*64*14*14];
__device__ float g_h3[(size_t)BB*128*7*7];
__device__ float g_z [(size_t)BB*64];
__device__ int   g_eidx[BB];
__device__ float g_dfc[(size_t)BB*32*7*7];
__device__ float g_dh1[(size_t)BB*64*14*14];
__device__ float g_dh2[(size_t)BB*32*28*28];

// ---------------- encoder conv1 (1->32, 28x28, relu) ----------------
__global__ void k_enc_conv1(const float* __restrict__ x, const float* __restrict__ w,
                            const float* __restrict__ b, float* __restrict__ out) {
    __shared__ float sin_[784];
    __shared__ float sw[288];
    __shared__ float sb[32];
    int n = blockIdx.x, tid = threadIdx.x;
    const float* xin = x + (size_t)n * 784;
    for (int i = tid; i < 784; i += 256) sin_[i] = xin[i];
    for (int i = tid; i < 288; i += 256) sw[i] = w[i];
    if (tid < 32) sb[tid] = b[tid];
    __syncthreads();
    for (int p = tid; p < 784; p += 256) {
        int oy = p / 28, ox = p % 28;
        float v[9];
#pragma unroll
        for (int ky = 0; ky < 3; ky++)
#pragma unroll
            for (int kx = 0; kx < 3; kx++) {
                int iy = oy - 1 + ky, ix = ox - 1 + kx;
                v[ky*3+kx] = (iy >= 0 && iy < 28 && ix >= 0 && ix < 28) ? sin_[iy*28+ix] : 0.f;
            }
        for (int co = 0; co < 32; co++) {
            float a = sb[co];
#pragma unroll
            for (int t = 0; t < 9; t++) a += v[t] * sw[co*9+t];
            out[((size_t)n*32 + co)*784 + p] = fmaxf(a, 0.f);
        }
    }
}

// ---------------- f32x2 conv, PPT=1, cp.async double-buffered staging ----------------
// ACT: 0=relu 1=elu 2=sigmoid
template<int CIN,int COUT,int CO_B,int OH,int OW,int SH,int SW_,int STRIDE,int UP,int ACT,
         int NT,int SB,int CI_T,int MINB>
__global__ void __launch_bounds__(NT, MINB)
conv5k(const float* __restrict__ in, const float* __restrict__ wt,
       const float* __restrict__ bs, float* __restrict__ out, const int* __restrict__ eidx) {
    constexpr int PW_ = SW_ + 2, PH_ = SH + 2, PA = PW_ * PH_;
    constexpr int NPIX = OH * OW, CO2 = CO_B / 2;
    constexpr int TILES = CIN / CI_T;
    constexpr int NBUF = (TILES > 1) ? 2 : 1;
    constexpr int TSZ = SB * CI_T * PA;
    static_assert(NT == SB * NPIX, "coverage");
    static_assert(CIN % CI_T == 0, "citile");
    static_assert(((NBUF * TSZ) & 1) == 0, "align8");

    extern __shared__ ull dsm[];
    float* sp = (float*)dsm;                              // NBUF * TSZ floats
    ull* sw2 = dsm + (size_t)(NBUF * TSZ) / 2;            // CIN*9*CO2 ulls
    __shared__ float sbias[CO_B];

    const int tid = threadIdx.x;
    const int nb = blockIdx.x * SB;
    const int cob = blockIdx.y;
    const float* wb = wt;
    const float* bb = bs;
    if (eidx) { int e = eidx[nb]; wb += (size_t)e * COUT * CIN * 9; bb += (size_t)e * COUT; }

    // stage packed weights ONCE: sw2[(ci*9+t)*CO2 + c2]
    for (int i = tid; i < CIN * 9 * CO2; i += NT) {
        int ci = i / (9 * CO2); int r = i - ci * 9 * CO2;
        int t = r / CO2; int c2 = r - t * CO2;
        int c0 = cob * CO_B + 2 * c2;
        float w0 = wb[((size_t)c0 * CIN + ci) * 9 + t];
        float w1 = wb[((size_t)(c0 + 1) * CIN + ci) * 9 + t];
        sw2[(ci * 9 + t) * CO2 + c2] = pack2(w0, w1);
    }
    if (tid < CO_B) sbias[tid] = bb[cob * CO_B + tid];

    // per-thread pixel setup (PPT = 1)
    const int s = tid / NPIX;
    const int pix = tid - s * NPIX;
    const int oy = pix / OW, ox = pix - oy * OW;
    int aoff; bool pyA = false, pxA = false;
    if (UP) {
        aoff = (((oy - 1) >> 1) + 1) * PW_ + (((ox - 1) >> 1) + 1);
        pyA = (oy & 1) != 0;
        pxA = (ox & 1) != 0;
    } else {
        aoff = oy * STRIDE * PW_ + ox * STRIDE;
    }
    const int sbase = s * CI_T * PA;

    ull acc[CO2];
#pragma unroll
    for (int c2 = 0; c2 < CO2; c2++) acc[c2] = 0ull;

    // async staging of one CI tile into buffer b
    auto prefetch = [&](int ci0, int b) {
        uint32_t sbuf = (uint32_t)__cvta_generic_to_shared(sp + (size_t)b * TSZ);
        for (int i = tid; i < TSZ; i += NT) {
            int ss = i / (CI_T * PA); int r = i - ss * (CI_T * PA);
            int ci = r / PA; int q = r - ci * PA;
            int py = q / PW_, px = q - py * PW_;
            int iy = py - 1, ix = px - 1;
            bool ok = (iy >= 0) & (iy < SH) & (ix >= 0) & (ix < SW_);
            const float* g = &in[(((size_t)(nb + ss) * CIN + ci0 + ci) * SH + (ok ? iy : 0)) * SW_ + (ok ? ix : 0)];
            cpa4(sbuf + (uint32_t)i * 4u, g, ok ? 4u : 0u);
        }
        cpa_commit();
    };

    prefetch(0, 0);
    for (int t = 0; t < TILES; t++) {
        if (t + 1 < TILES) { prefetch((t + 1) * CI_T, (t + 1) % NBUF); cpa_wait<1>(); }
        else               { cpa_wait<0>(); }
        __syncthreads();   // staged data (and weights on t=0) visible to all
        const float* buf = sp + (size_t)(t % NBUF) * TSZ;
#pragma unroll 1
        for (int ci = 0; ci < CI_T; ci++) {
            const ull* wrow = sw2 + (size_t)((t * CI_T + ci) * 9) * CO2;
            const float* cb = buf + sbase + ci * PA;
            float tv[9];
            if (UP) {
                float a = cb[aoff], b2_ = cb[aoff + 1], c = cb[aoff + PW_], d = cb[aoff + PW_ + 1];
                tv[0] = a;
                tv[1] = pxA ? a : b2_;
                tv[2] = b2_;
                tv[3] = pyA ? a : c;
                tv[4] = pyA ? (pxA ? a : b2_) : (pxA ? c : d);
                tv[5] = pyA ? b2_ : d;
                tv[6] = c;
                tv[7] = pxA ? c : d;
                tv[8] = d;
            } else {
#pragma unroll
                for (int ky = 0; ky < 3; ky++)
#pragma unroll
                    for (int kx = 0; kx < 3; kx++)
                        tv[ky*3+kx] = cb[aoff + ky * PW_ + kx];
            }
#pragma unroll
            for (int t9 = 0; t9 < 9; t9++) {
                ull v2 = dup2(tv[t9]);
                const ull* wt_ = wrow + t9 * CO2;
#pragma unroll
                for (int c2 = 0; c2 < CO2; c2++) fma2(acc[c2], v2, wt_[c2]);
            }
        }
        if (t + 1 < TILES) __syncthreads();  // compute(t) done before buffer reuse
    }

    // epilogue
    const int n = nb + s;
#pragma unroll
    for (int c2 = 0; c2 < CO2; c2++) {
        float2 f = unpack2(acc[c2]);
        int c0 = cob * CO_B + 2 * c2;
        float r0 = f.x + sbias[2*c2];
        float r1 = f.y + sbias[2*c2+1];
        if (ACT == 0)      { r0 = fmaxf(r0, 0.f); r1 = fmaxf(r1, 0.f); }
        else if (ACT == 1) { r0 = r0 > 0.f ? r0 : expm1f(r0); r1 = r1 > 0.f ? r1 : expm1f(r1); }
        else               { r0 = 1.f/(1.f+expf(-r0)); r1 = 1.f/(1.f+expf(-r1)); }
        out[((size_t)n * COUT + c0) * NPIX + pix] = r0;
        out[((size_t)n * COUT + c0 + 1) * NPIX + pix] = r1;
    }
}

// ---------------- fused head: mu/lv GEMM + z + gating + softmax + dec_fc ----------------
__global__ void __launch_bounds__(256)
k_head(const float* __restrict__ A,
       const float* __restrict__ Wm, const float* __restrict__ bm,
       const float* __restrict__ Wl, const float* __restrict__ bl,
       const float* __restrict__ eps,
       const float* __restrict__ w1, const float* __restrict__ b1,
       const float* __restrict__ w2, const float* __restrict__ b2,
       const float* __restrict__ w3, const float* __restrict__ b3,
       const float* __restrict__ fcw, const float* __restrict__ fcb,
       float* __restrict__ Om, float* __restrict__ Ol,
       float* __restrict__ Lg, float* __restrict__ Pb) {
    __shared__ float sa[16][33];
    __shared__ float swm[32][64];
    __shared__ float swl[32][64];
    __shared__ float sz[16][65];
    __shared__ float sh1[16][65];
    __shared__ float sh2[16][33];
    __shared__ int   sbest[16];
    int tid = threadIdx.x, tx = tid & 15, ty = tid >> 4;
    int row0 = blockIdx.x * 16;
    float am[4] = {0,0,0,0}, al[4] = {0,0,0,0};
    for (int kt = 0; kt < 196; kt++) {
        int kb = kt * 32;
        __syncthreads();
        for (int i = tid; i < 512; i += 256) { int r = i >> 5, c = i & 31; sa[r][c] = A[(size_t)(row0 + r) * 6272 + kb + c]; }
        for (int i = tid; i < 2048; i += 256) { int r = i >> 6, c = i & 63;
            swm[r][c] = Wm[(size_t)(kb + r) * 64 + c];
            swl[r][c] = Wl[(size_t)(kb + r) * 64 + c]; }
        __syncthreads();
#pragma unroll
        for (int kk = 0; kk < 32; kk++) {
            float a0 = sa[ty][kk];
            float4 m4 = *(const float4*)&swm[kk][tx * 4];
            float4 l4 = *(const float4*)&swl[kk][tx * 4];
            am[0] += a0 * m4.x; am[1] += a0 * m4.y; am[2] += a0 * m4.z; am[3] += a0 * m4.w;
            al[0] += a0 * l4.x; al[1] += a0 * l4.y; al[2] += a0 * l4.z; al[3] += a0 * l4.w;
        }
    }
    int r = row0 + ty;
#pragma unroll
    for (int j = 0; j < 4; j++) {
        int c = tx * 4 + j;
        float mu = am[j] + bm[c], lv = al[j] + bl[c];
        Om[(size_t)r * 64 + c] = mu;
        Ol[(size_t)r * 64 + c] = lv;
        float z = mu + eps[(size_t)r * 64 + c] * expf(0.5f * lv);
        sz[ty][c] = z;
        g_z[(size_t)r * 64 + c] = z;
    }
    __syncthreads();
    // gating h1: 16x64 units
#pragma unroll
    for (int q = 0; q < 4; q++) {
        int idx = tid * 4 + q; int s = idx >> 6, u = idx & 63;
        float a = b1[u];
        for (int k = 0; k < 64; k++) a += sz[s][k] * w1[k * 64 + u];
        sh1[s][u] = fmaxf(a, 0.f);
    }
    __syncthreads();
    // h2: 16x32
#pragma unroll
    for (int q = 0; q < 2; q++) {
        int idx = tid * 2 + q; int s = idx >> 5, u = idx & 31;
        float a = b2[u];
        for (int k = 0; k < 64; k++) a += sh1[s][k] * w2[k * 32 + u];
        sh2[s][u] = fmaxf(a, 0.f);
    }
    __syncthreads();
    // logits + softmax + argmax
    if (tid < 16) {
        int s = tid;
        float lg[8];
        for (int u = 0; u < 8; u++) {
            float a = b3[u];
            for (int k = 0; k < 32; k++) a += sh2[s][k] * w3[k * 8 + u];
            lg[u] = a;
        }
        float mx = lg[0];
        for (int u = 1; u < 8; u++) mx = fmaxf(mx, lg[u]);
        float e[8], sum = 0.f;
        for (int u = 0; u < 8; u++) { e[u] = expf(lg[u] - mx); sum += e[u]; }
        float inv = 1.f / sum;
        int best = 0; float bp = -1.f;
        for (int u = 0; u < 8; u++) {
            float p = e[u] * inv;
            Pb[(size_t)(row0 + s) * 8 + u] = p;
            Lg[(size_t)(row0 + s) * 8 + u] = logf(p + 1e-8f);
            if (p > bp) { bp = p; best = u; }
        }
        sbest[s] = best;
        g_eidx[row0 + s] = best;
    }
    __syncthreads();
    // decoder fc (selected expert)
    {
        int s = tid >> 4, o0 = tid & 15;
        int e = sbest[s];
        const float* W = fcw + (size_t)e * 64 * 1568;
        const float* B = fcb + (size_t)e * 1568;
        for (int oo = 0; oo < 98; oo++) {
            int o = o0 + oo * 16;
            float a = B[o];
#pragma unroll 8
            for (int k = 0; k < 64; k++) a += sz[s][k] * W[(size_t)k * 1568 + o];
            g_dfc[(size_t)(row0 + s) * 1568 + o] = a;
        }
    }
}

// ---------------- decoder conv3 (32->1, sigmoid) ----------------
__global__ void __launch_bounds__(196)
k_dconv3(const float* __restrict__ in, const float* __restrict__ wt,
         const float* __restrict__ bs, float* __restrict__ out, const int* __restrict__ eidx) {
    extern __shared__ float sp3[];   // 32*900
    __shared__ float sw[288];
    __shared__ float sb0;
    int n = blockIdx.x, tid = threadIdx.x;
    int e = eidx[n];
    const float* wb = wt + (size_t)e * 288;
    if (tid == 0) sb0 = bs[e];
    for (int i = tid; i < 288; i += 196) sw[i] = wb[i];
    const float* inn = in + (size_t)n * 32 * 784;
    for (int i = tid; i < 32*900; i += 196) {
        int ci = i / 900, q = i - ci*900;
        int py = q / 30, px = q - py*30;
        int iy = py - 1, ix = px - 1;
        float v = 0.f;
        if (iy >= 0 && iy < 28 && ix >= 0 && ix < 28) v = inn[ci*784 + iy*28 + ix];
        sp3[i] = v;
    }
    __syncthreads();
    int base[4]; int pixA[4];
#pragma unroll
    for (int pp = 0; pp < 4; pp++) {
        int p = tid + pp*196; pixA[pp] = p;
        int oy = p / 28, ox = p - oy*28;
        base[pp] = oy*30 + ox;
    }
    float acc[4] = {0.f, 0.f, 0.f, 0.f};
    for (int ci = 0; ci < 32; ci++) {
        float wr[9];
#pragma unroll
        for (int t = 0; t < 9; t++) wr[t] = sw[ci*9 + t];
        const float* cb = sp3 + ci*900;
#pragma unroll
        for (int ky = 0; ky < 3; ky++)
#pragma unroll
            for (int kx = 0; kx < 3; kx++) {
#pragma unroll
                for (int pp = 0; pp < 4; pp++)
                    acc[pp] += cb[base[pp] + ky*30 + kx] * wr[ky*3+kx];
            }
    }
#pragma unroll
    for (int pp = 0; pp < 4; pp++) {
        float r = acc[pp] + sb0;
        out[(size_t)n*784 + pixA[pp]] = 1.f / (1.f + expf(-r));
    }
}

// ---------------- launcher ----------------
extern "C" void kernel_launch(void* const* d_in, const int* in_sizes, int n_in,
                              void* d_out, int out_size) {
    const float* x      = (const float*)d_in[0];
    const float* eps    = (const float*)d_in[1];
    const float* enc_w1 = (const float*)d_in[2];  const float* enc_b1 = (const float*)d_in[3];
    const float* enc_w2 = (const float*)d_in[4];  const float* enc_b2 = (const float*)d_in[5];
    const float* enc_w3 = (const float*)d_in[6];  const float* enc_b3 = (const float*)d_in[7];
    const float* w_mu   = (const float*)d_in[8];  const float* b_mu   = (const float*)d_in[9];
    const float* w_lv   = (const float*)d_in[10]; const float* b_lv   = (const float*)d_in[11];
    const float* g_w1   = (const float*)d_in[12]; const float* g_b1   = (const float*)d_in[13];
    const float* g_w2   = (const float*)d_in[14]; const float* g_b2   = (const float*)d_in[15];
    const float* g_w3   = (const float*)d_in[16]; const float* g_b3   = (const float*)d_in[17];
    const float* d_fc_w = (const float*)d_in[18]; const float* d_fc_b = (const float*)d_in[19];
    const float* d_w1   = (const float*)d_in[20]; const float* d_b1   = (const float*)d_in[21];
    const float* d_w2   = (const float*)d_in[22]; const float* d_b2   = (const float*)d_in[23];
    const float* d_w3   = (const float*)d_in[24]; const float* d_b3   = (const float*)d_in[25];

    float* out   = (float*)d_out;
    float* o_rec = out;
    float* o_mu  = out + (size_t)BB*784;
    float* o_lv  = o_mu + (size_t)BB*64;
    float* o_lg  = o_lv + (size_t)BB*64;
    float* o_pb  = o_lg + (size_t)BB*8;

    float *h1, *h2, *h3, *dfc, *dh1, *dh2; int* eidx;
    cudaGetSymbolAddress((void**)&h1,  g_h1);
    cudaGetSymbolAddress((void**)&h2,  g_h2);
    cudaGetSymbolAddress((void**)&h3,  g_h3);
    cudaGetSymbolAddress((void**)&dfc, g_dfc);
    cudaGetSymbolAddress((void**)&dh1, g_dh1);
    cudaGetSymbolAddress((void**)&dh2, g_dh2);
    cudaGetSymbolAddress((void**)&eidx, g_eidx);

    // enc2: 32->64, 28->14 s2; NT=784, SB=4, CI_T=4, double-buffered
    auto enc2 = conv5k<32,64,32, 14,14, 28,28, 2,0,0, 784,4,4,1>;
    constexpr int SM_ENC2 = 2*4*4*900*4 + 32*9*16*8;         // 115200+36864=152064
    // enc3: 64->128, 14->7 s2; NT=784, SB=16, CI_T=2
    auto enc3 = conv5k<64,128,32, 7,7, 14,14, 2,0,0, 784,16,2,1>;
    constexpr int SM_ENC3 = 2*16*2*256*4 + 64*9*16*8;        // 65536+73728=139264
    // dec1: 32->64, up 7->14; NT=196, SB=1, CI_T=32 (single tile)
    auto dec1 = conv5k<32,64,32, 14,14, 7,7, 1,1,1, 196,1,32,4>;
    constexpr int SM_DEC1 = 1*32*81*4 + 32*9*16*8;           // 10368+36864=47232
    // dec2: 64->32, up 14->28; NT=784, SB=1, CI_T=32, grid.y=1
    auto dec2 = conv5k<64,32,32, 28,28, 14,14, 1,1,1, 784,1,32,1>;
    constexpr int SM_DEC2 = 2*1*32*256*4 + 64*9*16*8;        // 65536+73728=139264
    constexpr int SM_DEC3 = 32*900*4;                         // 115200

    cudaFuncSetAttribute(enc2, cudaFuncAttributeMaxDynamicSharedMemorySize, SM_ENC2);
    cudaFuncSetAttribute(enc3, cudaFuncAttributeMaxDynamicSharedMemorySize, SM_ENC3);
    cudaFuncSetAttribute(dec1, cudaFuncAttributeMaxDynamicSharedMemorySize, SM_DEC1);
    cudaFuncSetAttribute(dec2, cudaFuncAttributeMaxDynamicSharedMemorySize, SM_DEC2);
    cudaFuncSetAttribute(k_dconv3, cudaFuncAttributeMaxDynamicSharedMemorySize, SM_DEC3);

    // encoder
    k_enc_conv1<<<BB, 256>>>(x, enc_w1, enc_b1, h1);
    enc2<<<dim3(BB/4, 2),  784, SM_ENC2>>>(h1, enc_w2, enc_b2, h2, nullptr);
    enc3<<<dim3(BB/16, 4), 784, SM_ENC3>>>(h2, enc_w3, enc_b3, h3, nullptr);

    // fused head: mu/lv + z + gating + softmax/argmax + decoder fc
    k_head<<<BB/16, 256>>>(h3, w_mu, b_mu, w_lv, b_lv, eps,
                           g_w1, g_b1, g_w2, g_b2, g_w3, g_b3,
                           d_fc_w, d_fc_b, o_mu, o_lv, o_lg, o_pb);

    // decoder convs: only the selected expert per sample
    dec1<<<dim3(BB, 2), 196, SM_DEC1>>>(dfc, d_w1, d_b1, dh1, eidx);
    dec2<<<dim3(BB, 1), 784, SM_DEC2>>>(dh1, d_w2, d_b2, dh2, eidx);
    k_dconv3<<<BB, 196, SM_DEC3>>>(dh2, d_w3, d_b3, o_rec, eidx);
}